// round 12
// baseline (speedup 1.0000x reference)
#include <cuda_runtime.h>
#include <cuda_bf16.h>
#include <math.h>
#include <stdint.h>

// ---------------------------------------------------------------------------
// Problem constants (DeepseekV3 MLA prefill, B=1, S=2048)
// ---------------------------------------------------------------------------
#define S_LEN  2048
#define HID    2048
#define NH     16
#define NOPE   128
#define ROPE_D 64
#define QHD    192
#define VD     128
#define QLR    1536
#define KVLR   512
#define CKVD   576

// ---------------------------------------------------------------------------
// Scratch (static __device__ arrays — no runtime allocation)
// ---------------------------------------------------------------------------
__device__ float g_qa  [S_LEN * QLR];
__device__ float g_q   [S_LEN * NH * QHD];
__device__ float g_ckv [S_LEN * CKVD];
__device__ float g_kpe [S_LEN * ROPE_D];
__device__ float g_kv  [S_LEN * NH * (NOPE + VD)];

// Packed bf16 hi/lo activations (u32 = two K-adjacent bf16, lo16 = even k)
__device__ uint32_t g_hidh [S_LEN * (HID/2)];
__device__ uint32_t g_hidl [S_LEN * (HID/2)];
__device__ uint32_t g_qanh [S_LEN * (QLR/2)];
__device__ uint32_t g_qanl [S_LEN * (QLR/2)];
__device__ uint32_t g_ckvnh[S_LEN * (KVLR/2)];
__device__ uint32_t g_ckvnl[S_LEN * (KVLR/2)];
__device__ uint32_t g_attnh[S_LEN * (NH*VD/2)];
__device__ uint32_t g_attnl[S_LEN * (NH*VD/2)];

// Transposed + split weights: [Npad][K/2] words (hi and lo — 3-term scheme)
__device__ uint32_t g_Wqath [1536 * (HID/2)];
__device__ uint32_t g_Wqatl [1536 * (HID/2)];
__device__ uint32_t g_Wkvath[ 640 * (HID/2)];
__device__ uint32_t g_Wkvatl[ 640 * (HID/2)];
__device__ uint32_t g_Wqbth [3072 * (QLR/2)];
__device__ uint32_t g_Wqbtl [3072 * (QLR/2)];
__device__ uint32_t g_Wkvbth[4096 * (KVLR/2)];
__device__ uint32_t g_Wkvbtl[4096 * (KVLR/2)];
__device__ uint32_t g_Woth  [2048 * (NH*VD/2)];
__device__ uint32_t g_Wotl  [2048 * (NH*VD/2)];

// Packed per-head flash inputs
__device__ uint32_t g_qph[NH * S_LEN * 96];      // Q  [h][s][96w]
__device__ uint32_t g_qpl[NH * S_LEN * 96];
__device__ uint32_t g_kph[NH * S_LEN * 96];      // K  [h][s][96w]
__device__ uint32_t g_kpl[NH * S_LEN * 96];
__device__ uint32_t g_vth[NH * VD * (S_LEN/2)];  // V^T [h][vd][1024w]
__device__ uint32_t g_vtl[NH * VD * (S_LEN/2)];

// ---------------------------------------------------------------------------
// Helpers
// ---------------------------------------------------------------------------
__device__ __forceinline__ void split2(float a, float b, uint32_t& hi, uint32_t& lo) {
    __nv_bfloat16 ah = __float2bfloat16(a);
    __nv_bfloat16 bh = __float2bfloat16(b);
    __nv_bfloat16 al = __float2bfloat16(a - __bfloat162float(ah));
    __nv_bfloat16 bl = __float2bfloat16(b - __bfloat162float(bh));
    hi = (uint32_t)__bfloat16_as_ushort(ah) | ((uint32_t)__bfloat16_as_ushort(bh) << 16);
    lo = (uint32_t)__bfloat16_as_ushort(al) | ((uint32_t)__bfloat16_as_ushort(bl) << 16);
}

__device__ __forceinline__ void mma_bf16(float c[4], const uint32_t a[4],
                                         const uint32_t b[2]) {
    asm volatile(
        "mma.sync.aligned.m16n8k16.row.col.f32.bf16.bf16.f32 "
        "{%0,%1,%2,%3}, {%4,%5,%6,%7}, {%8,%9}, {%0,%1,%2,%3};"
        : "+f"(c[0]), "+f"(c[1]), "+f"(c[2]), "+f"(c[3])
        : "r"(a[0]), "r"(a[1]), "r"(a[2]), "r"(a[3]), "r"(b[0]), "r"(b[1]));
}

__device__ __forceinline__ void ldsm_x4(uint32_t r[4], uint32_t addr) {
    asm volatile("ldmatrix.sync.aligned.m8n8.x4.shared.b16 {%0,%1,%2,%3}, [%4];"
        : "=r"(r[0]), "=r"(r[1]), "=r"(r[2]), "=r"(r[3]) : "r"(addr));
}

#define CP16(dst, src) \
    asm volatile("cp.async.cg.shared.global [%0], [%1], 16;" :: "r"(dst), "l"(src))
#define CP_COMMIT() asm volatile("cp.async.commit_group;")

// ---------------------------------------------------------------------------
// Weight transpose + split: W[K][N] -> Th/Tl[Npad][K/2] words
// ---------------------------------------------------------------------------
__global__ void __launch_bounds__(256) wt_split_kernel(
    uint32_t* __restrict__ Th, uint32_t* __restrict__ Tl,
    const float* __restrict__ W, int K, int N)
{
    __shared__ float t[32][33];
    const int n0 = blockIdx.x * 32;
    const int k0 = blockIdx.y * 32;
    const int tx = threadIdx.x, ty = threadIdx.y;
    const int n = n0 + tx;
#pragma unroll
    for (int i = 0; i < 4; i++) {
        int k = ty + i * 8;
        t[k][tx] = (n < N) ? W[(size_t)(k0 + k) * N + n] : 0.f;
    }
    __syncthreads();
    const int Kw = K >> 1;
#pragma unroll
    for (int it = 0; it < 2; it++) {
        int s  = ty * 32 + tx + it * 256;
        int nl = s >> 4, wd = s & 15;
        uint32_t hi, lo;
        split2(t[2 * wd][nl], t[2 * wd + 1][nl], hi, lo);
        size_t o = (size_t)(n0 + nl) * Kw + (k0 >> 1) + wd;
        Th[o] = hi;
        Tl[o] = lo;
    }
}

// ---------------------------------------------------------------------------
// Activation split
// ---------------------------------------------------------------------------
__global__ void split_pack_kernel(uint32_t* __restrict__ oh, uint32_t* __restrict__ ol,
                                  const float* __restrict__ x, int nWords)
{
    int i = blockIdx.x * 256 + threadIdx.x;
    if (i < nWords) {
        float2 v = ((const float2*)x)[i];
        uint32_t hi, lo;
        split2(v.x, v.y, hi, lo);
        oh[i] = hi;
        ol[i] = lo;
    }
}

// ---------------------------------------------------------------------------
// RMSNorm fused with hi/lo pack
// ---------------------------------------------------------------------------
__global__ void __launch_bounds__(256) rmsnorm_pack_kernel(
    uint32_t* __restrict__ oh, uint32_t* __restrict__ ol,
    const float* __restrict__ in, const float* __restrict__ w, int D, int ldin)
{
    const int row = blockIdx.x;
    const float* x = in + (size_t)row * ldin;

    float s = 0.f;
    for (int i = threadIdx.x; i < D; i += 256) {
        float v = x[i];
        s += v * v;
    }
#pragma unroll
    for (int o = 16; o; o >>= 1) s += __shfl_xor_sync(0xffffffffu, s, o);
    __shared__ float red[8];
    __shared__ float inv_s;
    if ((threadIdx.x & 31) == 0) red[threadIdx.x >> 5] = s;
    __syncthreads();
    if (threadIdx.x == 0) {
        float tt = 0.f;
#pragma unroll
        for (int i = 0; i < 8; i++) tt += red[i];
        inv_s = rsqrtf(tt / (float)D + 1e-6f);
    }
    __syncthreads();
    const float inv = inv_s;
    const int Dw = D >> 1;
    for (int i = threadIdx.x; i < Dw; i += 256) {
        float a = w[2 * i]     * (x[2 * i]     * inv);
        float b = w[2 * i + 1] * (x[2 * i + 1] * inv);
        uint32_t hi, lo;
        split2(a, b, hi, lo);
        oh[(size_t)row * Dw + i] = hi;
        ol[(size_t)row * Dw + i] = lo;
    }
}

// ---------------------------------------------------------------------------
// 3-term bf16 GEMM, 128x128 tile (kept for the small-N GEMM)
// ---------------------------------------------------------------------------
#define GS_STAGE_WORDS 10240
#define GEMM_SMEM_BYTES (2 * GS_STAGE_WORDS * 4)

__global__ void __launch_bounds__(256, 2) gemm_bf16x3_ldsm_kernel(
    float* __restrict__ C,
    const uint32_t* __restrict__ Ah, const uint32_t* __restrict__ Al,
    const uint32_t* __restrict__ Bh, const uint32_t* __restrict__ Bl,
    int M, int N, int K, int ldc)
{
    extern __shared__ uint32_t sw[];
    const int Kw  = K >> 1;
    const int tid = threadIdx.x;
    const int lane = tid & 31;
    const int w   = tid >> 5;
    const int wm  = w >> 2;
    const int wn  = w & 3;
    const int g   = lane >> 2;
    const int t   = lane & 3;
    const int m0  = blockIdx.y * 128;
    const int n0  = blockIdx.x * 128;
    const uint32_t sbase = (uint32_t)__cvta_generic_to_shared(sw);

    const int r0 = tid >> 2,          c0 = (tid & 3) * 4;
    const int r1 = (tid + 256) >> 2,  c1 = ((tid + 256) & 3) * 4;

    const int a_row  = (lane & 7) + ((lane >> 3) & 1) * 8;
    const int a_colw = (lane >> 4) * 4;
    const int b_row  = (lane & 7) + ((lane >> 4) & 1) * 8;
    const int b_colw = ((lane >> 3) & 1) * 4;

    float acc[4][4][4];
#pragma unroll
    for (int mi = 0; mi < 4; mi++)
#pragma unroll
        for (int ni = 0; ni < 4; ni++)
#pragma unroll
            for (int e = 0; e < 4; e++) acc[mi][ni][e] = 0.f;

    const int nchunks = K / 32;

#define LOAD_CHUNK(ch, stage)                                                    \
    do {                                                                         \
        const int kw0 = (ch) * 16;                                               \
        uint32_t sb = sbase + (stage) * (GS_STAGE_WORDS * 4);                    \
        uint32_t d0 = sb + (r0 * 20 + c0) * 4;                                   \
        uint32_t d1 = sb + (r1 * 20 + c1) * 4;                                   \
        CP16(d0,          Ah + (size_t)(m0 + r0) * Kw + kw0 + c0);               \
        CP16(d1,          Ah + (size_t)(m0 + r1) * Kw + kw0 + c1);               \
        CP16(d0 + 10240,  Al + (size_t)(m0 + r0) * Kw + kw0 + c0);               \
        CP16(d1 + 10240,  Al + (size_t)(m0 + r1) * Kw + kw0 + c1);               \
        CP16(d0 + 20480,  Bh + (size_t)(n0 + r0) * Kw + kw0 + c0);               \
        CP16(d1 + 20480,  Bh + (size_t)(n0 + r1) * Kw + kw0 + c1);               \
        CP16(d0 + 30720,  Bl + (size_t)(n0 + r0) * Kw + kw0 + c0);               \
        CP16(d1 + 30720,  Bl + (size_t)(n0 + r1) * Kw + kw0 + c1);               \
    } while (0)

    LOAD_CHUNK(0, 0);
    CP_COMMIT();

    for (int ch = 0; ch < nchunks; ch++) {
        if (ch + 1 < nchunks) {
            LOAD_CHUNK(ch + 1, (ch + 1) & 1);
            CP_COMMIT();
            asm volatile("cp.async.wait_group 1;");
        } else {
            asm volatile("cp.async.wait_group 0;");
        }
        __syncthreads();

        uint32_t sAh = sbase + (ch & 1) * (GS_STAGE_WORDS * 4);
        uint32_t sAl = sAh + 2560 * 4;
        uint32_t sBh = sAh + 5120 * 4;
        uint32_t sBl = sAh + 7680 * 4;

#pragma unroll
        for (int kk = 0; kk < 2; kk++) {
            uint32_t bhq[2][4], blq[2][4];
#pragma unroll
            for (int p = 0; p < 2; p++) {
                uint32_t boff = ((wn * 32 + p * 16 + b_row) * 20
                                 + kk * 8 + b_colw) * 4;
                ldsm_x4(bhq[p], sBh + boff);
                ldsm_x4(blq[p], sBl + boff);
            }
#pragma unroll
            for (int mi = 0; mi < 4; mi++) {
                uint32_t aoff = ((wm * 64 + mi * 16 + a_row) * 20
                                 + kk * 8 + a_colw) * 4;
                uint32_t ah[4], al[4];
                ldsm_x4(ah, sAh + aoff);
                ldsm_x4(al, sAl + aoff);
#pragma unroll
                for (int ni = 0; ni < 4; ni++) {
                    const uint32_t* bh = &bhq[ni >> 1][(ni & 1) * 2];
                    const uint32_t* bl = &blq[ni >> 1][(ni & 1) * 2];
                    mma_bf16(acc[mi][ni], ah, bh);
                    mma_bf16(acc[mi][ni], al, bh);
                    mma_bf16(acc[mi][ni], ah, bl);
                }
            }
        }
        __syncthreads();
    }
#undef LOAD_CHUNK

#pragma unroll
    for (int mi = 0; mi < 4; mi++) {
        int rr0 = m0 + wm * 64 + mi * 16 + g;
        int rr1 = rr0 + 8;
#pragma unroll
        for (int ni = 0; ni < 4; ni++) {
            int c = n0 + wn * 32 + ni * 8 + 2 * t;
            if (c < N) {
                *(float2*)(C + (size_t)rr0 * ldc + c) =
                    make_float2(acc[mi][ni][0], acc[mi][ni][1]);
                *(float2*)(C + (size_t)rr1 * ldc + c) =
                    make_float2(acc[mi][ni][2], acc[mi][ni][3]);
            }
        }
    }
}

// ---------------------------------------------------------------------------
// 3-term bf16 GEMM, 128x256 tile, 512 threads (16 warps: 2m x 8n).
//   Halves the A-side L2 re-read traffic vs 128x128 (grid_x halves).
// smem/stage: Ah,Al 128x20 + Bh,Bl 256x20 = 15360 words = 61440 B; x2 stages.
// ---------------------------------------------------------------------------
#define GW_STAGE_WORDS 15360
#define GEMMW_SMEM_BYTES (2 * GW_STAGE_WORDS * 4)

__global__ void __launch_bounds__(512, 1) gemm_bf16x3_wide_kernel(
    float* __restrict__ C,
    const uint32_t* __restrict__ Ah, const uint32_t* __restrict__ Al,
    const uint32_t* __restrict__ Bh, const uint32_t* __restrict__ Bl,
    int M, int N, int K, int ldc)
{
    extern __shared__ uint32_t sw[];
    const int Kw  = K >> 1;
    const int tid = threadIdx.x;
    const int lane = tid & 31;
    const int w   = tid >> 5;          // 0..15
    const int wm  = w >> 3;            // 0..1  (64-row slab)
    const int wn  = w & 7;             // 0..7  (32-col slab)
    const int g   = lane >> 2;
    const int t   = lane & 3;
    const int m0  = blockIdx.y * 128;
    const int n0  = blockIdx.x * 256;
    const uint32_t sbase = (uint32_t)__cvta_generic_to_shared(sw);

    // cp.async slots: A one slot/thread (512 = 128 rows x 4), B two slots.
    const int rA  = tid >> 2, cA = (tid & 3) * 4;
    const int rB0 = rA;                 // rows 0..127
    const int rB1 = rA + 128;           // rows 128..255

    const int a_row  = (lane & 7) + ((lane >> 3) & 1) * 8;
    const int a_colw = (lane >> 4) * 4;
    const int b_row  = (lane & 7) + ((lane >> 4) & 1) * 8;
    const int b_colw = ((lane >> 3) & 1) * 4;

    float acc[4][4][4];
#pragma unroll
    for (int mi = 0; mi < 4; mi++)
#pragma unroll
        for (int ni = 0; ni < 4; ni++)
#pragma unroll
            for (int e = 0; e < 4; e++) acc[mi][ni][e] = 0.f;

    const int nchunks = K / 32;

#define LOAD_CHUNK_W(ch, stage)                                                  \
    do {                                                                         \
        const int kw0 = (ch) * 16;                                               \
        uint32_t sb = sbase + (stage) * (GW_STAGE_WORDS * 4);                    \
        CP16(sb + (rA * 20 + cA) * 4,                                            \
             Ah + (size_t)(m0 + rA) * Kw + kw0 + cA);                            \
        CP16(sb + (2560 + rA * 20 + cA) * 4,                                     \
             Al + (size_t)(m0 + rA) * Kw + kw0 + cA);                            \
        CP16(sb + (5120 + rB0 * 20 + cA) * 4,                                    \
             Bh + (size_t)(n0 + rB0) * Kw + kw0 + cA);                           \
        CP16(sb + (5120 + rB1 * 20 + cA) * 4,                                    \
             Bh + (size_t)(n0 + rB1) * Kw + kw0 + cA);                           \
        CP16(sb + (10240 + rB0 * 20 + cA) * 4,                                   \
             Bl + (size_t)(n0 + rB0) * Kw + kw0 + cA);                           \
        CP16(sb + (10240 + rB1 * 20 + cA) * 4,                                   \
             Bl + (size_t)(n0 + rB1) * Kw + kw0 + cA);                           \
    } while (0)

    LOAD_CHUNK_W(0, 0);
    CP_COMMIT();

    for (int ch = 0; ch < nchunks; ch++) {
        if (ch + 1 < nchunks) {
            LOAD_CHUNK_W(ch + 1, (ch + 1) & 1);
            CP_COMMIT();
            asm volatile("cp.async.wait_group 1;");
        } else {
            asm volatile("cp.async.wait_group 0;");
        }
        __syncthreads();

        uint32_t sAh = sbase + (ch & 1) * (GW_STAGE_WORDS * 4);
        uint32_t sAl = sAh + 2560 * 4;
        uint32_t sBh = sAh + 5120 * 4;
        uint32_t sBl = sAh + 10240 * 4;

#pragma unroll
        for (int kk = 0; kk < 2; kk++) {
            uint32_t bhq[2][4], blq[2][4];
#pragma unroll
            for (int p = 0; p < 2; p++) {
                uint32_t boff = ((wn * 32 + p * 16 + b_row) * 20
                                 + kk * 8 + b_colw) * 4;
                ldsm_x4(bhq[p], sBh + boff);
                ldsm_x4(blq[p], sBl + boff);
            }
#pragma unroll
            for (int mi = 0; mi < 4; mi++) {
                uint32_t aoff = ((wm * 64 + mi * 16 + a_row) * 20
                                 + kk * 8 + a_colw) * 4;
                uint32_t ah[4], al[4];
                ldsm_x4(ah, sAh + aoff);
                ldsm_x4(al, sAl + aoff);
#pragma unroll
                for (int ni = 0; ni < 4; ni++) {
                    const uint32_t* bh = &bhq[ni >> 1][(ni & 1) * 2];
                    const uint32_t* bl = &blq[ni >> 1][(ni & 1) * 2];
                    mma_bf16(acc[mi][ni], ah, bh);
                    mma_bf16(acc[mi][ni], al, bh);
                    mma_bf16(acc[mi][ni], ah, bl);
                }
            }
        }
        __syncthreads();
    }
#undef LOAD_CHUNK_W

#pragma unroll
    for (int mi = 0; mi < 4; mi++) {
        int rr0 = m0 + wm * 64 + mi * 16 + g;
        int rr1 = rr0 + 8;
#pragma unroll
        for (int ni = 0; ni < 4; ni++) {
            int c = n0 + wn * 32 + ni * 8 + 2 * t;
            if (c < N) {
                *(float2*)(C + (size_t)rr0 * ldc + c) =
                    make_float2(acc[mi][ni][0], acc[mi][ni][1]);
                *(float2*)(C + (size_t)rr1 * ldc + c) =
                    make_float2(acc[mi][ni][2], acc[mi][ni][3]);
            }
        }
    }
}

// ---------------------------------------------------------------------------
// RoPE (deinterleave + rotate_half fused)
// ---------------------------------------------------------------------------
__global__ void rope_kernel(float* __restrict__ q, float* __restrict__ kpe,
                            const float* __restrict__ ckv,
                            const int* __restrict__ pos_ids)
{
    const int srow = blockIdx.x;
    const int tid  = threadIdx.x;
    const int j    = tid & 31;

    const float pos  = (float)pos_ids[srow];
    const float freq = __expf(-((2.f * (float)j) / 64.f) * logf(10000.f));
    const float ang  = pos * freq;
    float cv, sv;
    __sincosf(ang, &sv, &cv);

    if (tid < NH * 32) {
        const int h = tid >> 5;
        float* base = q + (size_t)srow * (NH * QHD) + h * QHD + NOPE;
        float x0 = base[2 * j];
        float x1 = base[2 * j + 1];
        __syncwarp();
        base[j]      = x0 * cv - x1 * sv;
        base[32 + j] = x1 * cv + x0 * sv;
    } else {
        const float* src = ckv + (size_t)srow * CKVD + KVLR;
        float x0 = src[2 * j];
        float x1 = src[2 * j + 1];
        float* dst = kpe + (size_t)srow * ROPE_D;
        dst[j]      = x0 * cv - x1 * sv;
        dst[32 + j] = x1 * cv + x0 * sv;
    }
}

// ---------------------------------------------------------------------------
// Pack Q and K per head into hi/lo word arrays [h][s][96w]
// ---------------------------------------------------------------------------
__global__ void qk_pack_kernel(
    uint32_t* __restrict__ qh, uint32_t* __restrict__ ql,
    uint32_t* __restrict__ kh, uint32_t* __restrict__ kl,
    const float* __restrict__ q, const float* __restrict__ kv,
    const float* __restrict__ kpe)
{
    int idx = blockIdx.x * 256 + threadIdx.x;
    if (idx >= NH * S_LEN * 96) return;
    int w = idx % 96;
    int s = (idx / 96) % S_LEN;
    int h = idx / (96 * S_LEN);

    uint32_t hi, lo;
    const float* qp = q + (size_t)s * (NH * QHD) + h * QHD + 2 * w;
    split2(qp[0], qp[1], hi, lo);
    qh[idx] = hi; ql[idx] = lo;
    float a, b;
    if (w < 64) {
        const float* kp = kv + (size_t)s * (NH * 256) + h * 256 + 2 * w;
        a = kp[0]; b = kp[1];
    } else {
        const float* kp = kpe + (size_t)s * ROPE_D + 2 * (w - 64);
        a = kp[0]; b = kp[1];
    }
    split2(a, b, hi, lo);
    kh[idx] = hi; kl[idx] = lo;
}

// ---------------------------------------------------------------------------
// Pack V transposed: g_kv -> vt [h][vd][s/2 words]
// ---------------------------------------------------------------------------
__global__ void vt_pack_kernel(uint32_t* __restrict__ vth, uint32_t* __restrict__ vtl,
                               const float* __restrict__ kv)
{
    __shared__ float tile[64][33];
    const int s0 = blockIdx.x * 64, v0 = blockIdx.y * 32, h = blockIdx.z;
    const int tid = threadIdx.x;
#pragma unroll
    for (int i = 0; i < 8; i++) {
        int e = tid + i * 256;
        int s = e >> 5, vd = e & 31;
        tile[s][vd] = kv[(size_t)(s0 + s) * (NH * 256) + h * 256 + NOPE + v0 + vd];
    }
    __syncthreads();
#pragma unroll
    for (int i = 0; i < 4; i++) {
        int e = tid + i * 256;
        int vd = e >> 5, sw_ = e & 31;
        uint32_t hi, lo;
        split2(tile[2 * sw_][vd], tile[2 * sw_ + 1][vd], hi, lo);
        size_t o = (size_t)(h * VD + v0 + vd) * (S_LEN / 2) + (s0 >> 1) + sw_;
        vth[o] = hi; vtl[o] = lo;
    }
}

// ---------------------------------------------------------------------------
// Tensor-core causal flash attention (3-term bf16, fp32 softmax/acc).
// Epilogue writes packed hi/lo attn words directly (fused split).
// ---------------------------------------------------------------------------
#define FLASH_SMEM_BYTES (52480 * 4)

__global__ void __launch_bounds__(256, 1) flash_mma_kernel(
    uint32_t* __restrict__ Oh, uint32_t* __restrict__ Ol,
    const uint32_t* __restrict__ Qh, const uint32_t* __restrict__ Ql,
    const uint32_t* __restrict__ Kh, const uint32_t* __restrict__ Kl,
    const uint32_t* __restrict__ Vh, const uint32_t* __restrict__ Vl)
{
    extern __shared__ uint32_t sw[];
    uint32_t* sQh = sw;                // 64 x 100
    uint32_t* sQl = sw + 6400;
    uint32_t* sKh = sw + 12800;        // 2 bufs x 64 x 100
    uint32_t* sKl = sw + 25600;
    uint32_t* sVh = sw + 38400;        // 128 x 36
    uint32_t* sVl = sw + 43008;
    uint32_t* sPh = sw + 47616;        // 64 x 36
    uint32_t* sPl = sw + 49920;
    float*    sMax = (float*)(sw + 52224);
    float*    sSum = sMax + 128;

    const int tid  = threadIdx.x;
    const int lane = tid & 31;
    const int w    = tid >> 5;
    const int wm   = w & 3;
    const int wn   = w >> 2;
    const int g    = lane >> 2;
    const int t    = lane & 3;
    const int h    = blockIdx.y;
    const int qb   = blockIdx.x;
    const int q0   = qb * 64;
    const uint32_t sb = (uint32_t)__cvta_generic_to_shared(sw);

    const uint32_t* Qhp = Qh + ((size_t)h * S_LEN + q0) * 96;
    const uint32_t* Qlp = Ql + ((size_t)h * S_LEN + q0) * 96;
    const uint32_t* Khp = Kh + (size_t)h * S_LEN * 96;
    const uint32_t* Klp = Kl + (size_t)h * S_LEN * 96;
    const uint32_t* Vhp = Vh + (size_t)h * VD * (S_LEN / 2);
    const uint32_t* Vlp = Vl + (size_t)h * VD * (S_LEN / 2);

#pragma unroll
    for (int i = 0; i < 6; i++) {
        int c = tid + i * 256;
        int r = c / 24, c4 = (c % 24) * 4;
        CP16(sb + (r * 100 + c4) * 4,           Qhp + r * 96 + c4);
        CP16(sb + (6400 + r * 100 + c4) * 4,    Qlp + r * 96 + c4);
        CP16(sb + (12800 + r * 100 + c4) * 4,   Khp + r * 96 + c4);
        CP16(sb + (25600 + r * 100 + c4) * 4,   Klp + r * 96 + c4);
    }
    CP_COMMIT();

    float oacc[8][4];
#pragma unroll
    for (int ni = 0; ni < 8; ni++)
#pragma unroll
        for (int e = 0; e < 4; e++) oacc[ni][e] = 0.f;
    float mi0 = -1e30f, mi1 = -1e30f, li0 = 0.f, li1 = 0.f;

    const int r0 = wm * 16 + g, r1 = r0 + 8;
    const int qi0 = q0 + r0, qi1 = q0 + r1;
    const float scale = rsqrtf((float)QHD);

    for (int kb = 0; kb <= qb; kb++) {
        const int k0 = kb * 64;
#pragma unroll
        for (int i = 0; i < 4; i++) {
            int c = tid + i * 256;
            int r = c >> 3, c4 = (c & 7) * 4;
            CP16(sb + (38400 + r * 36 + c4) * 4, Vhp + (size_t)r * (S_LEN/2) + (k0 >> 1) + c4);
            CP16(sb + (43008 + r * 36 + c4) * 4, Vlp + (size_t)r * (S_LEN/2) + (k0 >> 1) + c4);
        }
        CP_COMMIT();
        if (kb < qb) {
            const int kn = (kb + 1) * 64;
            const int bo = ((kb + 1) & 1) * 6400;
#pragma unroll
            for (int i = 0; i < 6; i++) {
                int c = tid + i * 256;
                int r = c / 24, c4 = (c % 24) * 4;
                CP16(sb + (12800 + bo + r * 100 + c4) * 4, Khp + (size_t)(kn + r) * 96 + c4);
                CP16(sb + (25600 + bo + r * 100 + c4) * 4, Klp + (size_t)(kn + r) * 96 + c4);
            }
            CP_COMMIT();
            asm volatile("cp.async.wait_group 2;");
        } else {
            asm volatile("cp.async.wait_group 1;");
        }
        __syncthreads();

        const uint32_t* kbh = sKh + (kb & 1) * 6400;
        const uint32_t* kbl = sKl + (kb & 1) * 6400;
        float sacc[4][4];
#pragma unroll
        for (int ni = 0; ni < 4; ni++)
#pragma unroll
            for (int e = 0; e < 4; e++) sacc[ni][e] = 0.f;

#pragma unroll
        for (int ka = 0; ka < 12; ka++) {
            uint32_t bh[4][2], bl[4][2];
#pragma unroll
            for (int ni = 0; ni < 4; ni++) {
                int ba = (wn * 32 + ni * 8 + g) * 100 + ka * 8 + t;
                bh[ni][0] = kbh[ba]; bh[ni][1] = kbh[ba + 4];
                bl[ni][0] = kbl[ba]; bl[ni][1] = kbl[ba + 4];
            }
            int aa = r0 * 100 + ka * 8 + t;
            uint32_t ah[4], al[4];
            ah[0] = sQh[aa]; ah[1] = sQh[aa + 800]; ah[2] = sQh[aa + 4]; ah[3] = sQh[aa + 804];
            al[0] = sQl[aa]; al[1] = sQl[aa + 800]; al[2] = sQl[aa + 4]; al[3] = sQl[aa + 804];
#pragma unroll
            for (int ni = 0; ni < 4; ni++) {
                mma_bf16(sacc[ni], ah, bh[ni]);
                mma_bf16(sacc[ni], al, bh[ni]);
                mma_bf16(sacc[ni], ah, bl[ni]);
            }
        }

        const bool diag = (kb == qb);
        float v0[8], v1[8];
        float rm0 = -1e30f, rm1 = -1e30f;
#pragma unroll
        for (int ni = 0; ni < 4; ni++) {
#pragma unroll
            for (int e = 0; e < 2; e++) {
                int col = k0 + wn * 32 + ni * 8 + 2 * t + e;
                float x0 = sacc[ni][e]     * scale;
                float x1 = sacc[ni][2 + e] * scale;
                if (diag && col > qi0) x0 = -1e30f;
                if (diag && col > qi1) x1 = -1e30f;
                v0[ni * 2 + e] = x0;
                v1[ni * 2 + e] = x1;
                rm0 = fmaxf(rm0, x0);
                rm1 = fmaxf(rm1, x1);
            }
        }
        rm0 = fmaxf(rm0, __shfl_xor_sync(0xffffffffu, rm0, 1));
        rm0 = fmaxf(rm0, __shfl_xor_sync(0xffffffffu, rm0, 2));
        rm1 = fmaxf(rm1, __shfl_xor_sync(0xffffffffu, rm1, 1));
        rm1 = fmaxf(rm1, __shfl_xor_sync(0xffffffffu, rm1, 2));
        if (t == 0) {
            sMax[r0 * 2 + wn] = rm0;
            sMax[r1 * 2 + wn] = rm1;
        }
        __syncthreads();
        float mn0 = fmaxf(mi0, fmaxf(sMax[r0 * 2], sMax[r0 * 2 + 1]));
        float mn1 = fmaxf(mi1, fmaxf(sMax[r1 * 2], sMax[r1 * 2 + 1]));
        float al0 = __expf(mi0 - mn0);
        float al1 = __expf(mi1 - mn1);
        float ls0 = 0.f, ls1 = 0.f;
#pragma unroll
        for (int i = 0; i < 8; i++) {
            v0[i] = __expf(v0[i] - mn0); ls0 += v0[i];
            v1[i] = __expf(v1[i] - mn1); ls1 += v1[i];
        }
#pragma unroll
        for (int ni = 0; ni < 4; ni++) {
            uint32_t hi, lo;
            split2(v0[ni * 2], v0[ni * 2 + 1], hi, lo);
            sPh[r0 * 36 + wn * 16 + ni * 4 + t] = hi;
            sPl[r0 * 36 + wn * 16 + ni * 4 + t] = lo;
            split2(v1[ni * 2], v1[ni * 2 + 1], hi, lo);
            sPh[r1 * 36 + wn * 16 + ni * 4 + t] = hi;
            sPl[r1 * 36 + wn * 16 + ni * 4 + t] = lo;
        }
        ls0 += __shfl_xor_sync(0xffffffffu, ls0, 1);
        ls0 += __shfl_xor_sync(0xffffffffu, ls0, 2);
        ls1 += __shfl_xor_sync(0xffffffffu, ls1, 1);
        ls1 += __shfl_xor_sync(0xffffffffu, ls1, 2);
        if (t == 0) {
            sSum[r0 * 2 + wn] = ls0;
            sSum[r1 * 2 + wn] = ls1;
        }
        __syncthreads();
        li0 = li0 * al0 + sSum[r0 * 2] + sSum[r0 * 2 + 1];
        li1 = li1 * al1 + sSum[r1 * 2] + sSum[r1 * 2 + 1];
        mi0 = mn0; mi1 = mn1;
#pragma unroll
        for (int ni = 0; ni < 8; ni++) {
            oacc[ni][0] *= al0; oacc[ni][1] *= al0;
            oacc[ni][2] *= al1; oacc[ni][3] *= al1;
        }
        if (kb < qb) asm volatile("cp.async.wait_group 1;");
        else         asm volatile("cp.async.wait_group 0;");
        __syncthreads();

#pragma unroll
        for (int ka = 0; ka < 4; ka++) {
            int aa = r0 * 36 + ka * 8 + t;
            uint32_t ah[4], al[4];
            ah[0] = sPh[aa]; ah[1] = sPh[aa + 288]; ah[2] = sPh[aa + 4]; ah[3] = sPh[aa + 292];
            al[0] = sPl[aa]; al[1] = sPl[aa + 288]; al[2] = sPl[aa + 4]; al[3] = sPl[aa + 292];
#pragma unroll
            for (int ni = 0; ni < 8; ni++) {
                int ba = (wn * 64 + ni * 8 + g) * 36 + ka * 8 + t;
                uint32_t bh[2], bl[2];
                bh[0] = sVh[ba]; bh[1] = sVh[ba + 4];
                bl[0] = sVl[ba]; bl[1] = sVl[ba + 4];
                mma_bf16(oacc[ni], ah, bh);
                mma_bf16(oacc[ni], al, bh);
                mma_bf16(oacc[ni], ah, bl);
            }
        }
        __syncthreads();
    }

    // ---- epilogue: write packed hi/lo attn words directly ----
    float inv0 = 1.f / li0, inv1 = 1.f / li1;
#pragma unroll
    for (int ni = 0; ni < 8; ni++) {
        int col  = h * VD + wn * 64 + ni * 8 + 2 * t;   // even
        int word = col >> 1;
        uint32_t hi, lo;
        split2(oacc[ni][0] * inv0, oacc[ni][1] * inv0, hi, lo);
        Oh[(size_t)(q0 + r0) * (NH * VD / 2) + word] = hi;
        Ol[(size_t)(q0 + r0) * (NH * VD / 2) + word] = lo;
        split2(oacc[ni][2] * inv1, oacc[ni][3] * inv1, hi, lo);
        Oh[(size_t)(q0 + r1) * (NH * VD / 2) + word] = hi;
        Ol[(size_t)(q0 + r1) * (NH * VD / 2) + word] = lo;
    }
}

// ---------------------------------------------------------------------------
// Launch
// ---------------------------------------------------------------------------
extern "C" void kernel_launch(void* const* d_in, const int* in_sizes, int n_in,
                              void* d_out, int out_size)
{
    const float* hidden = (const float*)d_in[0];
    const int*   pos    = (const int*)d_in[1];
    const float* Wqa    = (const float*)d_in[2];
    const float* qa_ln  = (const float*)d_in[3];
    const float* Wqb    = (const float*)d_in[4];
    const float* Wkva   = (const float*)d_in[5];
    const float* kv_ln  = (const float*)d_in[6];
    const float* Wkvb   = (const float*)d_in[7];
    const float* Wo     = (const float*)d_in[8];
    float* out = (float*)d_out;

    float *qa, *q, *ckv, *kpe, *kv;
    cudaGetSymbolAddress((void**)&qa,   g_qa);
    cudaGetSymbolAddress((void**)&q,    g_q);
    cudaGetSymbolAddress((void**)&ckv,  g_ckv);
    cudaGetSymbolAddress((void**)&kpe,  g_kpe);
    cudaGetSymbolAddress((void**)&kv,   g_kv);

    uint32_t *hidh, *hidl, *qanh, *qanl, *ckvnh, *ckvnl, *attnh, *attnl;
    uint32_t *Wqath, *Wqatl, *Wkvath, *Wkvatl, *Wqbth, *Wqbtl, *Wkvbth, *Wkvbtl, *Woth, *Wotl;
    uint32_t *qph, *qpl, *kph, *kpl, *vth, *vtl;
    cudaGetSymbolAddress((void**)&hidh,  g_hidh);
    cudaGetSymbolAddress((void**)&hidl,  g_hidl);
    cudaGetSymbolAddress((void**)&qanh,  g_qanh);
    cudaGetSymbolAddress((void**)&qanl,  g_qanl);
    cudaGetSymbolAddress((void**)&ckvnh, g_ckvnh);
    cudaGetSymbolAddress((void**)&ckvnl, g_ckvnl);
    cudaGetSymbolAddress((void**)&attnh, g_attnh);
    cudaGetSymbolAddress((void**)&attnl, g_attnl);
    cudaGetSymbolAddress((void**)&Wqath,  g_Wqath);
    cudaGetSymbolAddress((void**)&Wqatl,  g_Wqatl);
    cudaGetSymbolAddress((void**)&Wkvath, g_Wkvath);
    cudaGetSymbolAddress((void**)&Wkvatl, g_Wkvatl);
    cudaGetSymbolAddress((void**)&Wqbth,  g_Wqbth);
    cudaGetSymbolAddress((void**)&Wqbtl,  g_Wqbtl);
    cudaGetSymbolAddress((void**)&Wkvbth, g_Wkvbth);
    cudaGetSymbolAddress((void**)&Wkvbtl, g_Wkvbtl);
    cudaGetSymbolAddress((void**)&Woth,   g_Woth);
    cudaGetSymbolAddress((void**)&Wotl,   g_Wotl);
    cudaGetSymbolAddress((void**)&qph, g_qph);
    cudaGetSymbolAddress((void**)&qpl, g_qpl);
    cudaGetSymbolAddress((void**)&kph, g_kph);
    cudaGetSymbolAddress((void**)&kpl, g_kpl);
    cudaGetSymbolAddress((void**)&vth, g_vth);
    cudaGetSymbolAddress((void**)&vtl, g_vtl);

    cudaFuncSetAttribute(gemm_bf16x3_ldsm_kernel,
                         cudaFuncAttributeMaxDynamicSharedMemorySize, GEMM_SMEM_BYTES);
    cudaFuncSetAttribute(gemm_bf16x3_wide_kernel,
                         cudaFuncAttributeMaxDynamicSharedMemorySize, GEMMW_SMEM_BYTES);
    cudaFuncSetAttribute(flash_mma_kernel,
                         cudaFuncAttributeMaxDynamicSharedMemorySize, FLASH_SMEM_BYTES);

    dim3 wtb(32, 8);
    wt_split_kernel<<<dim3(1536 / 32, HID / 32),  wtb>>>(Wqath,  Wqatl,  Wqa,  HID,  QLR);
    wt_split_kernel<<<dim3( 640 / 32, HID / 32),  wtb>>>(Wkvath, Wkvatl, Wkva, HID,  CKVD);
    wt_split_kernel<<<dim3(3072 / 32, QLR / 32),  wtb>>>(Wqbth,  Wqbtl,  Wqb,  QLR,  NH * QHD);
    wt_split_kernel<<<dim3(4096 / 32, KVLR / 32), wtb>>>(Wkvbth, Wkvbtl, Wkvb, KVLR, NH * (NOPE + VD));
    wt_split_kernel<<<dim3(2048 / 32, (NH*VD) / 32), wtb>>>(Woth, Wotl, Wo, NH * VD, HID);
    split_pack_kernel<<<(S_LEN * (HID/2) + 255) / 256, 256>>>(hidh, hidl, hidden, S_LEN * (HID/2));

    // 1) q_a = hidden @ Wqa    [2048 x 1536], wide tiles (grid 6x16)
    gemm_bf16x3_wide_kernel<<<dim3(1536 / 256, S_LEN / 128), 512, GEMMW_SMEM_BYTES>>>(
        qa, hidh, hidl, Wqath, Wqatl, S_LEN, QLR, HID, QLR);
    // 2) ckv = hidden @ Wkva   [2048 x 576], 128-tile (grid 5x16)
    gemm_bf16x3_ldsm_kernel<<<dim3(640 / 128, S_LEN / 128), 256, GEMM_SMEM_BYTES>>>(
        ckv, hidh, hidl, Wkvath, Wkvatl, S_LEN, CKVD, HID, CKVD);
    // 3-4) rmsnorms -> packed
    rmsnorm_pack_kernel<<<S_LEN, 256>>>(qanh, qanl, qa, qa_ln, QLR, QLR);
    rmsnorm_pack_kernel<<<S_LEN, 256>>>(ckvnh, ckvnl, ckv, kv_ln, KVLR, CKVD);
    // 5) q = q_a_n @ Wqb       [2048 x 3072], wide (grid 12x16)
    gemm_bf16x3_wide_kernel<<<dim3(3072 / 256, S_LEN / 128), 512, GEMMW_SMEM_BYTES>>>(
        q, qanh, qanl, Wqbth, Wqbtl, S_LEN, NH * QHD, QLR, NH * QHD);
    // 6) kv = ckv_n @ Wkvb     [2048 x 4096], wide (grid 16x16)
    gemm_bf16x3_wide_kernel<<<dim3(4096 / 256, S_LEN / 128), 512, GEMMW_SMEM_BYTES>>>(
        kv, ckvnh, ckvnl, Wkvbth, Wkvbtl, S_LEN, NH * 256, KVLR, NH * 256);
    // 7) RoPE
    rope_kernel<<<S_LEN, (NH + 1) * 32>>>(q, kpe, ckv, pos);
    // 8) pack flash inputs
    qk_pack_kernel<<<(NH * S_LEN * 96 + 255) / 256, 256>>>(qph, qpl, kph, kpl, q, kv, kpe);
    vt_pack_kernel<<<dim3(S_LEN / 64, VD / 32, NH), 256>>>(vth, vtl, kv);
    // 9) tensor-core flash attention (writes packed attn directly)
    flash_mma_kernel<<<dim3(S_LEN / 64, NH), 256, FLASH_SMEM_BYTES>>>(
        attnh, attnl, qph, qpl, kph, kpl, vth, vtl);
    // 10) out = attn @ Wo      [2048 x 2048], wide (grid 8x16)
    gemm_bf16x3_wide_kernel<<<dim3(HID / 256, S_LEN / 128), 512, GEMMW_SMEM_BYTES>>>(
        out, attnh, attnl, Woth, Wotl, S_LEN, HID, NH * VD, HID);
}

// round 13
// speedup vs baseline: 1.1595x; 1.1595x over previous
#include <cuda_runtime.h>
#include <cuda_bf16.h>
#include <math.h>
#include <stdint.h>

// ---------------------------------------------------------------------------
// Problem constants (DeepseekV3 MLA prefill, B=1, S=2048)
// ---------------------------------------------------------------------------
#define S_LEN  2048
#define HID    2048
#define NH     16
#define NOPE   128
#define ROPE_D 64
#define QHD    192
#define VD     128
#define QLR    1536
#define KVLR   512
#define CKVD   576
#define NC12   2176   // combined GEMM1+2 output width (1536 + 640 pad)
#define NC12V  2112   // valid cols (1536 + 576)

// ---------------------------------------------------------------------------
// Scratch (static __device__ arrays — no runtime allocation)
// ---------------------------------------------------------------------------
__device__ float g_qackv[S_LEN * NC12];          // [qa | ckv] fp32
__device__ float g_q   [S_LEN * NH * QHD];
__device__ float g_kpe [S_LEN * ROPE_D];
__device__ float g_kv  [S_LEN * NH * (NOPE + VD)];

// Packed bf16 hi/lo activations
__device__ uint32_t g_hidh [S_LEN * (HID/2)];
__device__ uint32_t g_hidl [S_LEN * (HID/2)];
__device__ uint32_t g_qanh [S_LEN * (QLR/2)];
__device__ uint32_t g_qanl [S_LEN * (QLR/2)];
__device__ uint32_t g_ckvnh[S_LEN * (KVLR/2)];
__device__ uint32_t g_ckvnl[S_LEN * (KVLR/2)];
__device__ uint32_t g_attnh[S_LEN * (NH*VD/2)];
__device__ uint32_t g_attnl[S_LEN * (NH*VD/2)];

// Transposed + split weights: [Npad][K/2] words
__device__ uint32_t g_W12th [NC12 * (HID/2)];    // Wqa rows 0..1535, Wkva rows 1536..2175
__device__ uint32_t g_W12tl [NC12 * (HID/2)];
__device__ uint32_t g_Wqbth [3072 * (QLR/2)];
__device__ uint32_t g_Wqbtl [3072 * (QLR/2)];
__device__ uint32_t g_Wkvbth[4096 * (KVLR/2)];
__device__ uint32_t g_Wkvbtl[4096 * (KVLR/2)];
__device__ uint32_t g_Woth  [2048 * (NH*VD/2)];
__device__ uint32_t g_Wotl  [2048 * (NH*VD/2)];

// Packed per-head flash inputs
__device__ uint32_t g_qph[NH * S_LEN * 96];
__device__ uint32_t g_qpl[NH * S_LEN * 96];
__device__ uint32_t g_kph[NH * S_LEN * 96];
__device__ uint32_t g_kpl[NH * S_LEN * 96];
__device__ uint32_t g_vth[NH * VD * (S_LEN/2)];
__device__ uint32_t g_vtl[NH * VD * (S_LEN/2)];

// ---------------------------------------------------------------------------
// Helpers
// ---------------------------------------------------------------------------
__device__ __forceinline__ void split2(float a, float b, uint32_t& hi, uint32_t& lo) {
    __nv_bfloat16 ah = __float2bfloat16(a);
    __nv_bfloat16 bh = __float2bfloat16(b);
    __nv_bfloat16 al = __float2bfloat16(a - __bfloat162float(ah));
    __nv_bfloat16 bl = __float2bfloat16(b - __bfloat162float(bh));
    hi = (uint32_t)__bfloat16_as_ushort(ah) | ((uint32_t)__bfloat16_as_ushort(bh) << 16);
    lo = (uint32_t)__bfloat16_as_ushort(al) | ((uint32_t)__bfloat16_as_ushort(bl) << 16);
}

__device__ __forceinline__ void mma_bf16(float c[4], const uint32_t a[4],
                                         const uint32_t b[2]) {
    asm volatile(
        "mma.sync.aligned.m16n8k16.row.col.f32.bf16.bf16.f32 "
        "{%0,%1,%2,%3}, {%4,%5,%6,%7}, {%8,%9}, {%0,%1,%2,%3};"
        : "+f"(c[0]), "+f"(c[1]), "+f"(c[2]), "+f"(c[3])
        : "r"(a[0]), "r"(a[1]), "r"(a[2]), "r"(a[3]), "r"(b[0]), "r"(b[1]));
}

__device__ __forceinline__ void ldsm_x4(uint32_t r[4], uint32_t addr) {
    asm volatile("ldmatrix.sync.aligned.m8n8.x4.shared.b16 {%0,%1,%2,%3}, [%4];"
        : "=r"(r[0]), "=r"(r[1]), "=r"(r[2]), "=r"(r[3]) : "r"(addr));
}

#define CP16(dst, src) \
    asm volatile("cp.async.cg.shared.global [%0], [%1], 16;" :: "r"(dst), "l"(src))
#define CP_COMMIT() asm volatile("cp.async.commit_group;")

// ---------------------------------------------------------------------------
// Batched weight transpose + split: 5 jobs in one launch.
// Each job: W[K][N] -> Th/Tl[Npad][K/2] words (Th/Tl may be row-offset).
// ---------------------------------------------------------------------------
struct WtJob {
    const float* W;
    uint32_t* Th;
    uint32_t* Tl;
    int K;       // rows of W (inner dim)
    int N;       // valid cols of W
    int nbx;     // Npad/32
    int blk0;    // first flat block id
};
struct WtJobs { WtJob j[5]; int total; };

__global__ void __launch_bounds__(256) wt_split_all_kernel(WtJobs jobs)
{
    __shared__ float t[32][33];
    const int bid = blockIdx.x;
    int ji = 0;
#pragma unroll
    for (int i = 1; i < 5; i++)
        if (bid >= jobs.j[i].blk0) ji = i;
    const WtJob& J = jobs.j[ji];
    const int loc = bid - J.blk0;
    const int n0 = (loc % J.nbx) * 32;
    const int k0 = (loc / J.nbx) * 32;

    const int tx = threadIdx.x, ty = threadIdx.y;
    const int n = n0 + tx;
#pragma unroll
    for (int i = 0; i < 4; i++) {
        int k = ty + i * 8;
        t[k][tx] = (n < J.N) ? J.W[(size_t)(k0 + k) * J.N + n] : 0.f;
    }
    __syncthreads();
    const int Kw = J.K >> 1;
#pragma unroll
    for (int it = 0; it < 2; it++) {
        int s  = ty * 32 + tx + it * 256;
        int nl = s >> 4, wd = s & 15;
        uint32_t hi, lo;
        split2(t[2 * wd][nl], t[2 * wd + 1][nl], hi, lo);
        size_t o = (size_t)(n0 + nl) * Kw + (k0 >> 1) + wd;
        J.Th[o] = hi;
        J.Tl[o] = lo;
    }
}

// ---------------------------------------------------------------------------
// Activation split
// ---------------------------------------------------------------------------
__global__ void split_pack_kernel(uint32_t* __restrict__ oh, uint32_t* __restrict__ ol,
                                  const float* __restrict__ x, int nWords)
{
    int i = blockIdx.x * 256 + threadIdx.x;
    if (i < nWords) {
        float2 v = ((const float2*)x)[i];
        uint32_t hi, lo;
        split2(v.x, v.y, hi, lo);
        oh[i] = hi;
        ol[i] = lo;
    }
}

// ---------------------------------------------------------------------------
// RMSNorm fused with hi/lo pack
// ---------------------------------------------------------------------------
__global__ void __launch_bounds__(256) rmsnorm_pack_kernel(
    uint32_t* __restrict__ oh, uint32_t* __restrict__ ol,
    const float* __restrict__ in, const float* __restrict__ w, int D, int ldin)
{
    const int row = blockIdx.x;
    const float* x = in + (size_t)row * ldin;

    float s = 0.f;
    for (int i = threadIdx.x; i < D; i += 256) {
        float v = x[i];
        s += v * v;
    }
#pragma unroll
    for (int o = 16; o; o >>= 1) s += __shfl_xor_sync(0xffffffffu, s, o);
    __shared__ float red[8];
    __shared__ float inv_s;
    if ((threadIdx.x & 31) == 0) red[threadIdx.x >> 5] = s;
    __syncthreads();
    if (threadIdx.x == 0) {
        float tt = 0.f;
#pragma unroll
        for (int i = 0; i < 8; i++) tt += red[i];
        inv_s = rsqrtf(tt / (float)D + 1e-6f);
    }
    __syncthreads();
    const float inv = inv_s;
    const int Dw = D >> 1;
    for (int i = threadIdx.x; i < Dw; i += 256) {
        float a = w[2 * i]     * (x[2 * i]     * inv);
        float b = w[2 * i + 1] * (x[2 * i + 1] * inv);
        uint32_t hi, lo;
        split2(a, b, hi, lo);
        oh[(size_t)row * Dw + i] = hi;
        ol[(size_t)row * Dw + i] = lo;
    }
}

// ---------------------------------------------------------------------------
// 3-term bf16 GEMM, 128x128 tile, ldmatrix, 2-stage cp.async (R11-proven)
// ---------------------------------------------------------------------------
#define GS_STAGE_WORDS 10240
#define GEMM_SMEM_BYTES (2 * GS_STAGE_WORDS * 4)

__global__ void __launch_bounds__(256, 2) gemm_bf16x3_ldsm_kernel(
    float* __restrict__ C,
    const uint32_t* __restrict__ Ah, const uint32_t* __restrict__ Al,
    const uint32_t* __restrict__ Bh, const uint32_t* __restrict__ Bl,
    int M, int N, int K, int ldc)
{
    extern __shared__ uint32_t sw[];
    const int Kw  = K >> 1;
    const int tid = threadIdx.x;
    const int lane = tid & 31;
    const int w   = tid >> 5;
    const int wm  = w >> 2;
    const int wn  = w & 3;
    const int g   = lane >> 2;
    const int t   = lane & 3;
    const int m0  = blockIdx.y * 128;
    const int n0  = blockIdx.x * 128;
    const uint32_t sbase = (uint32_t)__cvta_generic_to_shared(sw);

    const int r0 = tid >> 2,          c0 = (tid & 3) * 4;
    const int r1 = (tid + 256) >> 2,  c1 = ((tid + 256) & 3) * 4;

    const int a_row  = (lane & 7) + ((lane >> 3) & 1) * 8;
    const int a_colw = (lane >> 4) * 4;
    const int b_row  = (lane & 7) + ((lane >> 4) & 1) * 8;
    const int b_colw = ((lane >> 3) & 1) * 4;

    float acc[4][4][4];
#pragma unroll
    for (int mi = 0; mi < 4; mi++)
#pragma unroll
        for (int ni = 0; ni < 4; ni++)
#pragma unroll
            for (int e = 0; e < 4; e++) acc[mi][ni][e] = 0.f;

    const int nchunks = K / 32;

#define LOAD_CHUNK(ch, stage)                                                    \
    do {                                                                         \
        const int kw0 = (ch) * 16;                                               \
        uint32_t sb = sbase + (stage) * (GS_STAGE_WORDS * 4);                    \
        uint32_t d0 = sb + (r0 * 20 + c0) * 4;                                   \
        uint32_t d1 = sb + (r1 * 20 + c1) * 4;                                   \
        CP16(d0,          Ah + (size_t)(m0 + r0) * Kw + kw0 + c0);               \
        CP16(d1,          Ah + (size_t)(m0 + r1) * Kw + kw0 + c1);               \
        CP16(d0 + 10240,  Al + (size_t)(m0 + r0) * Kw + kw0 + c0);               \
        CP16(d1 + 10240,  Al + (size_t)(m0 + r1) * Kw + kw0 + c1);               \
        CP16(d0 + 20480,  Bh + (size_t)(n0 + r0) * Kw + kw0 + c0);               \
        CP16(d1 + 20480,  Bh + (size_t)(n0 + r1) * Kw + kw0 + c1);               \
        CP16(d0 + 30720,  Bl + (size_t)(n0 + r0) * Kw + kw0 + c0);               \
        CP16(d1 + 30720,  Bl + (size_t)(n0 + r1) * Kw + kw0 + c1);               \
    } while (0)

    LOAD_CHUNK(0, 0);
    CP_COMMIT();

    for (int ch = 0; ch < nchunks; ch++) {
        if (ch + 1 < nchunks) {
            LOAD_CHUNK(ch + 1, (ch + 1) & 1);
            CP_COMMIT();
            asm volatile("cp.async.wait_group 1;");
        } else {
            asm volatile("cp.async.wait_group 0;");
        }
        __syncthreads();

        uint32_t sAh = sbase + (ch & 1) * (GS_STAGE_WORDS * 4);
        uint32_t sAl = sAh + 2560 * 4;
        uint32_t sBh = sAh + 5120 * 4;
        uint32_t sBl = sAh + 7680 * 4;

#pragma unroll
        for (int kk = 0; kk < 2; kk++) {
            uint32_t bhq[2][4], blq[2][4];
#pragma unroll
            for (int p = 0; p < 2; p++) {
                uint32_t boff = ((wn * 32 + p * 16 + b_row) * 20
                                 + kk * 8 + b_colw) * 4;
                ldsm_x4(bhq[p], sBh + boff);
                ldsm_x4(blq[p], sBl + boff);
            }
#pragma unroll
            for (int mi = 0; mi < 4; mi++) {
                uint32_t aoff = ((wm * 64 + mi * 16 + a_row) * 20
                                 + kk * 8 + a_colw) * 4;
                uint32_t ah[4], al[4];
                ldsm_x4(ah, sAh + aoff);
                ldsm_x4(al, sAl + aoff);
#pragma unroll
                for (int ni = 0; ni < 4; ni++) {
                    const uint32_t* bh = &bhq[ni >> 1][(ni & 1) * 2];
                    const uint32_t* bl = &blq[ni >> 1][(ni & 1) * 2];
                    mma_bf16(acc[mi][ni], ah, bh);
                    mma_bf16(acc[mi][ni], al, bh);
                    mma_bf16(acc[mi][ni], ah, bl);
                }
            }
        }
        __syncthreads();
    }
#undef LOAD_CHUNK

#pragma unroll
    for (int mi = 0; mi < 4; mi++) {
        int rr0 = m0 + wm * 64 + mi * 16 + g;
        int rr1 = rr0 + 8;
#pragma unroll
        for (int ni = 0; ni < 4; ni++) {
            int c = n0 + wn * 32 + ni * 8 + 2 * t;
            if (c < N) {
                *(float2*)(C + (size_t)rr0 * ldc + c) =
                    make_float2(acc[mi][ni][0], acc[mi][ni][1]);
                *(float2*)(C + (size_t)rr1 * ldc + c) =
                    make_float2(acc[mi][ni][2], acc[mi][ni][3]);
            }
        }
    }
}

// ---------------------------------------------------------------------------
// RoPE (deinterleave + rotate_half fused); k_pe read from combined buffer
// ---------------------------------------------------------------------------
__global__ void rope_kernel(float* __restrict__ q, float* __restrict__ kpe,
                            const float* __restrict__ kpe_src, int ld_src,
                            const int* __restrict__ pos_ids)
{
    const int srow = blockIdx.x;
    const int tid  = threadIdx.x;
    const int j    = tid & 31;

    const float pos  = (float)pos_ids[srow];
    const float freq = __expf(-((2.f * (float)j) / 64.f) * logf(10000.f));
    const float ang  = pos * freq;
    float cv, sv;
    __sincosf(ang, &sv, &cv);

    if (tid < NH * 32) {
        const int h = tid >> 5;
        float* base = q + (size_t)srow * (NH * QHD) + h * QHD + NOPE;
        float x0 = base[2 * j];
        float x1 = base[2 * j + 1];
        __syncwarp();
        base[j]      = x0 * cv - x1 * sv;
        base[32 + j] = x1 * cv + x0 * sv;
    } else {
        const float* src = kpe_src + (size_t)srow * ld_src;
        float x0 = src[2 * j];
        float x1 = src[2 * j + 1];
        float* dst = kpe + (size_t)srow * ROPE_D;
        dst[j]      = x0 * cv - x1 * sv;
        dst[32 + j] = x1 * cv + x0 * sv;
    }
}

// ---------------------------------------------------------------------------
// Pack Q and K per head into hi/lo word arrays [h][s][96w]
// ---------------------------------------------------------------------------
__global__ void qk_pack_kernel(
    uint32_t* __restrict__ qh, uint32_t* __restrict__ ql,
    uint32_t* __restrict__ kh, uint32_t* __restrict__ kl,
    const float* __restrict__ q, const float* __restrict__ kv,
    const float* __restrict__ kpe)
{
    int idx = blockIdx.x * 256 + threadIdx.x;
    if (idx >= NH * S_LEN * 96) return;
    int w = idx % 96;
    int s = (idx / 96) % S_LEN;
    int h = idx / (96 * S_LEN);

    uint32_t hi, lo;
    const float* qp = q + (size_t)s * (NH * QHD) + h * QHD + 2 * w;
    split2(qp[0], qp[1], hi, lo);
    qh[idx] = hi; ql[idx] = lo;
    float a, b;
    if (w < 64) {
        const float* kp = kv + (size_t)s * (NH * 256) + h * 256 + 2 * w;
        a = kp[0]; b = kp[1];
    } else {
        const float* kp = kpe + (size_t)s * ROPE_D + 2 * (w - 64);
        a = kp[0]; b = kp[1];
    }
    split2(a, b, hi, lo);
    kh[idx] = hi; kl[idx] = lo;
}

// ---------------------------------------------------------------------------
// Pack V transposed: g_kv -> vt [h][vd][s/2 words]
// ---------------------------------------------------------------------------
__global__ void vt_pack_kernel(uint32_t* __restrict__ vth, uint32_t* __restrict__ vtl,
                               const float* __restrict__ kv)
{
    __shared__ float tile[64][33];
    const int s0 = blockIdx.x * 64, v0 = blockIdx.y * 32, h = blockIdx.z;
    const int tid = threadIdx.x;
#pragma unroll
    for (int i = 0; i < 8; i++) {
        int e = tid + i * 256;
        int s = e >> 5, vd = e & 31;
        tile[s][vd] = kv[(size_t)(s0 + s) * (NH * 256) + h * 256 + NOPE + v0 + vd];
    }
    __syncthreads();
#pragma unroll
    for (int i = 0; i < 4; i++) {
        int e = tid + i * 256;
        int vd = e >> 5, sw_ = e & 31;
        uint32_t hi, lo;
        split2(tile[2 * sw_][vd], tile[2 * sw_ + 1][vd], hi, lo);
        size_t o = (size_t)(h * VD + v0 + vd) * (S_LEN / 2) + (s0 >> 1) + sw_;
        vth[o] = hi; vtl[o] = lo;
    }
}

// ---------------------------------------------------------------------------
// Tensor-core causal flash attention (3-term bf16, fp32 softmax/acc).
// ---------------------------------------------------------------------------
#define FLASH_SMEM_BYTES (52480 * 4)

__global__ void __launch_bounds__(256, 1) flash_mma_kernel(
    uint32_t* __restrict__ Oh, uint32_t* __restrict__ Ol,
    const uint32_t* __restrict__ Qh, const uint32_t* __restrict__ Ql,
    const uint32_t* __restrict__ Kh, const uint32_t* __restrict__ Kl,
    const uint32_t* __restrict__ Vh, const uint32_t* __restrict__ Vl)
{
    extern __shared__ uint32_t sw[];
    uint32_t* sQh = sw;
    uint32_t* sQl = sw + 6400;
    uint32_t* sKh = sw + 12800;
    uint32_t* sKl = sw + 25600;
    uint32_t* sVh = sw + 38400;
    uint32_t* sVl = sw + 43008;
    uint32_t* sPh = sw + 47616;
    uint32_t* sPl = sw + 49920;
    float*    sMax = (float*)(sw + 52224);
    float*    sSum = sMax + 128;

    const int tid  = threadIdx.x;
    const int lane = tid & 31;
    const int w    = tid >> 5;
    const int wm   = w & 3;
    const int wn   = w >> 2;
    const int g    = lane >> 2;
    const int t    = lane & 3;
    const int h    = blockIdx.y;
    const int qb   = blockIdx.x;
    const int q0   = qb * 64;
    const uint32_t sb = (uint32_t)__cvta_generic_to_shared(sw);

    const uint32_t* Qhp = Qh + ((size_t)h * S_LEN + q0) * 96;
    const uint32_t* Qlp = Ql + ((size_t)h * S_LEN + q0) * 96;
    const uint32_t* Khp = Kh + (size_t)h * S_LEN * 96;
    const uint32_t* Klp = Kl + (size_t)h * S_LEN * 96;
    const uint32_t* Vhp = Vh + (size_t)h * VD * (S_LEN / 2);
    const uint32_t* Vlp = Vl + (size_t)h * VD * (S_LEN / 2);

#pragma unroll
    for (int i = 0; i < 6; i++) {
        int c = tid + i * 256;
        int r = c / 24, c4 = (c % 24) * 4;
        CP16(sb + (r * 100 + c4) * 4,           Qhp + r * 96 + c4);
        CP16(sb + (6400 + r * 100 + c4) * 4,    Qlp + r * 96 + c4);
        CP16(sb + (12800 + r * 100 + c4) * 4,   Khp + r * 96 + c4);
        CP16(sb + (25600 + r * 100 + c4) * 4,   Klp + r * 96 + c4);
    }
    CP_COMMIT();

    float oacc[8][4];
#pragma unroll
    for (int ni = 0; ni < 8; ni++)
#pragma unroll
        for (int e = 0; e < 4; e++) oacc[ni][e] = 0.f;
    float mi0 = -1e30f, mi1 = -1e30f, li0 = 0.f, li1 = 0.f;

    const int r0 = wm * 16 + g, r1 = r0 + 8;
    const int qi0 = q0 + r0, qi1 = q0 + r1;
    const float scale = rsqrtf((float)QHD);

    for (int kb = 0; kb <= qb; kb++) {
        const int k0 = kb * 64;
#pragma unroll
        for (int i = 0; i < 4; i++) {
            int c = tid + i * 256;
            int r = c >> 3, c4 = (c & 7) * 4;
            CP16(sb + (38400 + r * 36 + c4) * 4, Vhp + (size_t)r * (S_LEN/2) + (k0 >> 1) + c4);
            CP16(sb + (43008 + r * 36 + c4) * 4, Vlp + (size_t)r * (S_LEN/2) + (k0 >> 1) + c4);
        }
        CP_COMMIT();
        if (kb < qb) {
            const int kn = (kb + 1) * 64;
            const int bo = ((kb + 1) & 1) * 6400;
#pragma unroll
            for (int i = 0; i < 6; i++) {
                int c = tid + i * 256;
                int r = c / 24, c4 = (c % 24) * 4;
                CP16(sb + (12800 + bo + r * 100 + c4) * 4, Khp + (size_t)(kn + r) * 96 + c4);
                CP16(sb + (25600 + bo + r * 100 + c4) * 4, Klp + (size_t)(kn + r) * 96 + c4);
            }
            CP_COMMIT();
            asm volatile("cp.async.wait_group 2;");
        } else {
            asm volatile("cp.async.wait_group 1;");
        }
        __syncthreads();

        const uint32_t* kbh = sKh + (kb & 1) * 6400;
        const uint32_t* kbl = sKl + (kb & 1) * 6400;
        float sacc[4][4];
#pragma unroll
        for (int ni = 0; ni < 4; ni++)
#pragma unroll
            for (int e = 0; e < 4; e++) sacc[ni][e] = 0.f;

#pragma unroll
        for (int ka = 0; ka < 12; ka++) {
            uint32_t bh[4][2], bl[4][2];
#pragma unroll
            for (int ni = 0; ni < 4; ni++) {
                int ba = (wn * 32 + ni * 8 + g) * 100 + ka * 8 + t;
                bh[ni][0] = kbh[ba]; bh[ni][1] = kbh[ba + 4];
                bl[ni][0] = kbl[ba]; bl[ni][1] = kbl[ba + 4];
            }
            int aa = r0 * 100 + ka * 8 + t;
            uint32_t ah[4], al[4];
            ah[0] = sQh[aa]; ah[1] = sQh[aa + 800]; ah[2] = sQh[aa + 4]; ah[3] = sQh[aa + 804];
            al[0] = sQl[aa]; al[1] = sQl[aa + 800]; al[2] = sQl[aa + 4]; al[3] = sQl[aa + 804];
#pragma unroll
            for (int ni = 0; ni < 4; ni++) {
                mma_bf16(sacc[ni], ah, bh[ni]);
                mma_bf16(sacc[ni], al, bh[ni]);
                mma_bf16(sacc[ni], ah, bl[ni]);
            }
        }

        const bool diag = (kb == qb);
        float v0[8], v1[8];
        float rm0 = -1e30f, rm1 = -1e30f;
#pragma unroll
        for (int ni = 0; ni < 4; ni++) {
#pragma unroll
            for (int e = 0; e < 2; e++) {
                int col = k0 + wn * 32 + ni * 8 + 2 * t + e;
                float x0 = sacc[ni][e]     * scale;
                float x1 = sacc[ni][2 + e] * scale;
                if (diag && col > qi0) x0 = -1e30f;
                if (diag && col > qi1) x1 = -1e30f;
                v0[ni * 2 + e] = x0;
                v1[ni * 2 + e] = x1;
                rm0 = fmaxf(rm0, x0);
                rm1 = fmaxf(rm1, x1);
            }
        }
        rm0 = fmaxf(rm0, __shfl_xor_sync(0xffffffffu, rm0, 1));
        rm0 = fmaxf(rm0, __shfl_xor_sync(0xffffffffu, rm0, 2));
        rm1 = fmaxf(rm1, __shfl_xor_sync(0xffffffffu, rm1, 1));
        rm1 = fmaxf(rm1, __shfl_xor_sync(0xffffffffu, rm1, 2));
        if (t == 0) {
            sMax[r0 * 2 + wn] = rm0;
            sMax[r1 * 2 + wn] = rm1;
        }
        __syncthreads();
        float mn0 = fmaxf(mi0, fmaxf(sMax[r0 * 2], sMax[r0 * 2 + 1]));
        float mn1 = fmaxf(mi1, fmaxf(sMax[r1 * 2], sMax[r1 * 2 + 1]));
        float al0 = __expf(mi0 - mn0);
        float al1 = __expf(mi1 - mn1);
        float ls0 = 0.f, ls1 = 0.f;
#pragma unroll
        for (int i = 0; i < 8; i++) {
            v0[i] = __expf(v0[i] - mn0); ls0 += v0[i];
            v1[i] = __expf(v1[i] - mn1); ls1 += v1[i];
        }
#pragma unroll
        for (int ni = 0; ni < 4; ni++) {
            uint32_t hi, lo;
            split2(v0[ni * 2], v0[ni * 2 + 1], hi, lo);
            sPh[r0 * 36 + wn * 16 + ni * 4 + t] = hi;
            sPl[r0 * 36 + wn * 16 + ni * 4 + t] = lo;
            split2(v1[ni * 2], v1[ni * 2 + 1], hi, lo);
            sPh[r1 * 36 + wn * 16 + ni * 4 + t] = hi;
            sPl[r1 * 36 + wn * 16 + ni * 4 + t] = lo;
        }
        ls0 += __shfl_xor_sync(0xffffffffu, ls0, 1);
        ls0 += __shfl_xor_sync(0xffffffffu, ls0, 2);
        ls1 += __shfl_xor_sync(0xffffffffu, ls1, 1);
        ls1 += __shfl_xor_sync(0xffffffffu, ls1, 2);
        if (t == 0) {
            sSum[r0 * 2 + wn] = ls0;
            sSum[r1 * 2 + wn] = ls1;
        }
        __syncthreads();
        li0 = li0 * al0 + sSum[r0 * 2] + sSum[r0 * 2 + 1];
        li1 = li1 * al1 + sSum[r1 * 2] + sSum[r1 * 2 + 1];
        mi0 = mn0; mi1 = mn1;
#pragma unroll
        for (int ni = 0; ni < 8; ni++) {
            oacc[ni][0] *= al0; oacc[ni][1] *= al0;
            oacc[ni][2] *= al1; oacc[ni][3] *= al1;
        }
        if (kb < qb) asm volatile("cp.async.wait_group 1;");
        else         asm volatile("cp.async.wait_group 0;");
        __syncthreads();

#pragma unroll
        for (int ka = 0; ka < 4; ka++) {
            int aa = r0 * 36 + ka * 8 + t;
            uint32_t ah[4], al[4];
            ah[0] = sPh[aa]; ah[1] = sPh[aa + 288]; ah[2] = sPh[aa + 4]; ah[3] = sPh[aa + 292];
            al[0] = sPl[aa]; al[1] = sPl[aa + 288]; al[2] = sPl[aa + 4]; al[3] = sPl[aa + 292];
#pragma unroll
            for (int ni = 0; ni < 8; ni++) {
                int ba = (wn * 64 + ni * 8 + g) * 36 + ka * 8 + t;
                uint32_t bh[2], bl[2];
                bh[0] = sVh[ba]; bh[1] = sVh[ba + 4];
                bl[0] = sVl[ba]; bl[1] = sVl[ba + 4];
                mma_bf16(oacc[ni], ah, bh);
                mma_bf16(oacc[ni], al, bh);
                mma_bf16(oacc[ni], ah, bl);
            }
        }
        __syncthreads();
    }

    float inv0 = 1.f / li0, inv1 = 1.f / li1;
#pragma unroll
    for (int ni = 0; ni < 8; ni++) {
        int col  = h * VD + wn * 64 + ni * 8 + 2 * t;
        int word = col >> 1;
        uint32_t hi, lo;
        split2(oacc[ni][0] * inv0, oacc[ni][1] * inv0, hi, lo);
        Oh[(size_t)(q0 + r0) * (NH * VD / 2) + word] = hi;
        Ol[(size_t)(q0 + r0) * (NH * VD / 2) + word] = lo;
        split2(oacc[ni][2] * inv1, oacc[ni][3] * inv1, hi, lo);
        Oh[(size_t)(q0 + r1) * (NH * VD / 2) + word] = hi;
        Ol[(size_t)(q0 + r1) * (NH * VD / 2) + word] = lo;
    }
}

// ---------------------------------------------------------------------------
// Launch
// ---------------------------------------------------------------------------
extern "C" void kernel_launch(void* const* d_in, const int* in_sizes, int n_in,
                              void* d_out, int out_size)
{
    const float* hidden = (const float*)d_in[0];
    const int*   pos    = (const int*)d_in[1];
    const float* Wqa    = (const float*)d_in[2];
    const float* qa_ln  = (const float*)d_in[3];
    const float* Wqb    = (const float*)d_in[4];
    const float* Wkva   = (const float*)d_in[5];
    const float* kv_ln  = (const float*)d_in[6];
    const float* Wkvb   = (const float*)d_in[7];
    const float* Wo     = (const float*)d_in[8];
    float* out = (float*)d_out;

    float *qackv, *q, *kpe, *kv;
    cudaGetSymbolAddress((void**)&qackv, g_qackv);
    cudaGetSymbolAddress((void**)&q,     g_q);
    cudaGetSymbolAddress((void**)&kpe,   g_kpe);
    cudaGetSymbolAddress((void**)&kv,    g_kv);

    uint32_t *hidh, *hidl, *qanh, *qanl, *ckvnh, *ckvnl, *attnh, *attnl;
    uint32_t *W12th, *W12tl, *Wqbth, *Wqbtl, *Wkvbth, *Wkvbtl, *Woth, *Wotl;
    uint32_t *qph, *qpl, *kph, *kpl, *vth, *vtl;
    cudaGetSymbolAddress((void**)&hidh,  g_hidh);
    cudaGetSymbolAddress((void**)&hidl,  g_hidl);
    cudaGetSymbolAddress((void**)&qanh,  g_qanh);
    cudaGetSymbolAddress((void**)&qanl,  g_qanl);
    cudaGetSymbolAddress((void**)&ckvnh, g_ckvnh);
    cudaGetSymbolAddress((void**)&ckvnl, g_ckvnl);
    cudaGetSymbolAddress((void**)&attnh, g_attnh);
    cudaGetSymbolAddress((void**)&attnl, g_attnl);
    cudaGetSymbolAddress((void**)&W12th,  g_W12th);
    cudaGetSymbolAddress((void**)&W12tl,  g_W12tl);
    cudaGetSymbolAddress((void**)&Wqbth,  g_Wqbth);
    cudaGetSymbolAddress((void**)&Wqbtl,  g_Wqbtl);
    cudaGetSymbolAddress((void**)&Wkvbth, g_Wkvbth);
    cudaGetSymbolAddress((void**)&Wkvbtl, g_Wkvbtl);
    cudaGetSymbolAddress((void**)&Woth,   g_Woth);
    cudaGetSymbolAddress((void**)&Wotl,   g_Wotl);
    cudaGetSymbolAddress((void**)&qph, g_qph);
    cudaGetSymbolAddress((void**)&qpl, g_qpl);
    cudaGetSymbolAddress((void**)&kph, g_kph);
    cudaGetSymbolAddress((void**)&kpl, g_kpl);
    cudaGetSymbolAddress((void**)&vth, g_vth);
    cudaGetSymbolAddress((void**)&vtl, g_vtl);

    cudaFuncSetAttribute(gemm_bf16x3_ldsm_kernel,
                         cudaFuncAttributeMaxDynamicSharedMemorySize, GEMM_SMEM_BYTES);
    cudaFuncSetAttribute(flash_mma_kernel,
                         cudaFuncAttributeMaxDynamicSharedMemorySize, FLASH_SMEM_BYTES);

    // ---- batched weight transpose+split (1 launch, 5 jobs) ----
    WtJobs jobs;
    // Wqa: rows 0..1535 of combined
    jobs.j[0] = { Wqa,  W12th,               W12tl,               HID,  QLR,          48,  0 };
    // Wkva: rows 1536..2175 of combined
    jobs.j[1] = { Wkva, W12th + 1536*(HID/2), W12tl + 1536*(HID/2), HID, CKVD,        20,  3072 };
    jobs.j[2] = { Wqb,  Wqbth,               Wqbtl,               QLR,  NH * QHD,     96,  4352 };
    jobs.j[3] = { Wkvb, Wkvbth,              Wkvbtl,              KVLR, NH*(NOPE+VD), 128, 8960 };
    jobs.j[4] = { Wo,   Woth,                Wotl,                NH*VD, HID,         64,  11008 };
    jobs.total = 15104;
    wt_split_all_kernel<<<jobs.total, dim3(32, 8)>>>(jobs);

    split_pack_kernel<<<(S_LEN * (HID/2) + 255) / 256, 256>>>(hidh, hidl, hidden, S_LEN * (HID/2));

    // 1+2) [qa | ckv] = hidden @ [Wqa | Wkva]   (grid 17x16 = 272 CTAs)
    gemm_bf16x3_ldsm_kernel<<<dim3(NC12 / 128, S_LEN / 128), 256, GEMM_SMEM_BYTES>>>(
        qackv, hidh, hidl, W12th, W12tl, S_LEN, NC12V, HID, NC12);
    // 3-4) rmsnorms -> packed (from combined buffer)
    rmsnorm_pack_kernel<<<S_LEN, 256>>>(qanh, qanl, qackv, qa_ln, QLR, NC12);
    rmsnorm_pack_kernel<<<S_LEN, 256>>>(ckvnh, ckvnl, qackv + QLR, kv_ln, KVLR, NC12);
    // 5) q = q_a_n @ Wqb
    gemm_bf16x3_ldsm_kernel<<<dim3(3072 / 128, S_LEN / 128), 256, GEMM_SMEM_BYTES>>>(
        q, qanh, qanl, Wqbth, Wqbtl, S_LEN, NH * QHD, QLR, NH * QHD);
    // 6) kv = ckv_n @ Wkvb
    gemm_bf16x3_ldsm_kernel<<<dim3(4096 / 128, S_LEN / 128), 256, GEMM_SMEM_BYTES>>>(
        kv, ckvnh, ckvnl, Wkvbth, Wkvbtl, S_LEN, NH * 256, KVLR, NH * 256);
    // 7) RoPE (k_pe from combined buffer cols [2048, 2112))
    rope_kernel<<<S_LEN, (NH + 1) * 32>>>(q, kpe, qackv + QLR + KVLR, NC12, pos);
    // 8) pack flash inputs
    qk_pack_kernel<<<(NH * S_LEN * 96 + 255) / 256, 256>>>(qph, qpl, kph, kpl, q, kv, kpe);
    vt_pack_kernel<<<dim3(S_LEN / 64, VD / 32, NH), 256>>>(vth, vtl, kv);
    // 9) tensor-core flash attention
    flash_mma_kernel<<<dim3(S_LEN / 64, NH), 256, FLASH_SMEM_BYTES>>>(
        attnh, attnl, qph, qpl, kph, kpl, vth, vtl);
    // 10) out = attn @ Wo
    gemm_bf16x3_ldsm_kernel<<<dim3(HID / 128, S_LEN / 128), 256, GEMM_SMEM_BYTES>>>(
        out, attnh, attnl, Woth, Wotl, S_LEN, HID, NH * VD, HID);
}

// round 14
// speedup vs baseline: 1.1612x; 1.0015x over previous
#include <cuda_runtime.h>
#include <cuda_bf16.h>
#include <math.h>
#include <stdint.h>

// ---------------------------------------------------------------------------
// Problem constants (DeepseekV3 MLA prefill, B=1, S=2048)
// ---------------------------------------------------------------------------
#define S_LEN  2048
#define HID    2048
#define NH     16
#define NOPE   128
#define ROPE_D 64
#define QHD    192
#define VD     128
#define QLR    1536
#define KVLR   512
#define CKVD   576
#define NC12   2176   // combined GEMM1+2 output width (1536 + 640 pad)
#define NC12V  2112   // valid cols (1536 + 576)

// ---------------------------------------------------------------------------
// Scratch (static __device__ arrays — no runtime allocation)
// ---------------------------------------------------------------------------
__device__ float g_qackv[S_LEN * NC12];          // [qa | ckv] fp32
__device__ float g_q   [S_LEN * NH * QHD];
__device__ float g_kpe [S_LEN * ROPE_D];
__device__ float g_kv  [S_LEN * NH * (NOPE + VD)];

// Packed bf16 hi/lo activations
__device__ uint32_t g_hidh [S_LEN * (HID/2)];
__device__ uint32_t g_hidl [S_LEN * (HID/2)];
__device__ uint32_t g_qanh [S_LEN * (QLR/2)];
__device__ uint32_t g_qanl [S_LEN * (QLR/2)];
__device__ uint32_t g_ckvnh[S_LEN * (KVLR/2)];
__device__ uint32_t g_ckvnl[S_LEN * (KVLR/2)];
__device__ uint32_t g_attnh[S_LEN * (NH*VD/2)];
__device__ uint32_t g_attnl[S_LEN * (NH*VD/2)];

// Transposed + split weights: [Npad][K/2] words
__device__ uint32_t g_W12th [NC12 * (HID/2)];    // Wqa rows 0..1535, Wkva rows 1536..2175
__device__ uint32_t g_W12tl [NC12 * (HID/2)];
__device__ uint32_t g_Wqbth [3072 * (QLR/2)];
__device__ uint32_t g_Wqbtl [3072 * (QLR/2)];
__device__ uint32_t g_Wkvbth[4096 * (KVLR/2)];
__device__ uint32_t g_Wkvbtl[4096 * (KVLR/2)];
__device__ uint32_t g_Woth  [2048 * (NH*VD/2)];
__device__ uint32_t g_Wotl  [2048 * (NH*VD/2)];

// Packed per-head flash inputs
__device__ uint32_t g_qph[NH * S_LEN * 96];
__device__ uint32_t g_qpl[NH * S_LEN * 96];
__device__ uint32_t g_kph[NH * S_LEN * 96];
__device__ uint32_t g_kpl[NH * S_LEN * 96];
__device__ uint32_t g_vth[NH * VD * (S_LEN/2)];
__device__ uint32_t g_vtl[NH * VD * (S_LEN/2)];

// ---------------------------------------------------------------------------
// Helpers
// ---------------------------------------------------------------------------
__device__ __forceinline__ void split2(float a, float b, uint32_t& hi, uint32_t& lo) {
    __nv_bfloat16 ah = __float2bfloat16(a);
    __nv_bfloat16 bh = __float2bfloat16(b);
    __nv_bfloat16 al = __float2bfloat16(a - __bfloat162float(ah));
    __nv_bfloat16 bl = __float2bfloat16(b - __bfloat162float(bh));
    hi = (uint32_t)__bfloat16_as_ushort(ah) | ((uint32_t)__bfloat16_as_ushort(bh) << 16);
    lo = (uint32_t)__bfloat16_as_ushort(al) | ((uint32_t)__bfloat16_as_ushort(bl) << 16);
}

__device__ __forceinline__ void mma_bf16(float c[4], const uint32_t a[4],
                                         const uint32_t b[2]) {
    asm volatile(
        "mma.sync.aligned.m16n8k16.row.col.f32.bf16.bf16.f32 "
        "{%0,%1,%2,%3}, {%4,%5,%6,%7}, {%8,%9}, {%0,%1,%2,%3};"
        : "+f"(c[0]), "+f"(c[1]), "+f"(c[2]), "+f"(c[3])
        : "r"(a[0]), "r"(a[1]), "r"(a[2]), "r"(a[3]), "r"(b[0]), "r"(b[1]));
}

__device__ __forceinline__ void ldsm_x4(uint32_t r[4], uint32_t addr) {
    asm volatile("ldmatrix.sync.aligned.m8n8.x4.shared.b16 {%0,%1,%2,%3}, [%4];"
        : "=r"(r[0]), "=r"(r[1]), "=r"(r[2]), "=r"(r[3]) : "r"(addr));
}

#define CP16(dst, src) \
    asm volatile("cp.async.cg.shared.global [%0], [%1], 16;" :: "r"(dst), "l"(src))
#define CP_COMMIT() asm volatile("cp.async.commit_group;")

// ---------------------------------------------------------------------------
// Batched weight transpose + split: 5 jobs in one launch.
// Each job: W[K][N] -> Th/Tl[Npad][K/2] words (Th/Tl may be row-offset).
// ---------------------------------------------------------------------------
struct WtJob {
    const float* W;
    uint32_t* Th;
    uint32_t* Tl;
    int K;       // rows of W (inner dim)
    int N;       // valid cols of W
    int nbx;     // Npad/32
    int blk0;    // first flat block id
};
struct WtJobs { WtJob j[5]; int total; };

__global__ void __launch_bounds__(256) wt_split_all_kernel(WtJobs jobs)
{
    __shared__ float t[32][33];
    const int bid = blockIdx.x;
    int ji = 0;
#pragma unroll
    for (int i = 1; i < 5; i++)
        if (bid >= jobs.j[i].blk0) ji = i;
    const WtJob& J = jobs.j[ji];
    const int loc = bid - J.blk0;
    const int n0 = (loc % J.nbx) * 32;
    const int k0 = (loc / J.nbx) * 32;

    const int tx = threadIdx.x, ty = threadIdx.y;
    const int n = n0 + tx;
#pragma unroll
    for (int i = 0; i < 4; i++) {
        int k = ty + i * 8;
        t[k][tx] = (n < J.N) ? J.W[(size_t)(k0 + k) * J.N + n] : 0.f;
    }
    __syncthreads();
    const int Kw = J.K >> 1;
#pragma unroll
    for (int it = 0; it < 2; it++) {
        int s  = ty * 32 + tx + it * 256;
        int nl = s >> 4, wd = s & 15;
        uint32_t hi, lo;
        split2(t[2 * wd][nl], t[2 * wd + 1][nl], hi, lo);
        size_t o = (size_t)(n0 + nl) * Kw + (k0 >> 1) + wd;
        J.Th[o] = hi;
        J.Tl[o] = lo;
    }
}

// ---------------------------------------------------------------------------
// Activation split
// ---------------------------------------------------------------------------
__global__ void split_pack_kernel(uint32_t* __restrict__ oh, uint32_t* __restrict__ ol,
                                  const float* __restrict__ x, int nWords)
{
    int i = blockIdx.x * 256 + threadIdx.x;
    if (i < nWords) {
        float2 v = ((const float2*)x)[i];
        uint32_t hi, lo;
        split2(v.x, v.y, hi, lo);
        oh[i] = hi;
        ol[i] = lo;
    }
}

// ---------------------------------------------------------------------------
// RMSNorm fused with hi/lo pack
// ---------------------------------------------------------------------------
__global__ void __launch_bounds__(256) rmsnorm_pack_kernel(
    uint32_t* __restrict__ oh, uint32_t* __restrict__ ol,
    const float* __restrict__ in, const float* __restrict__ w, int D, int ldin)
{
    const int row = blockIdx.x;
    const float* x = in + (size_t)row * ldin;

    float s = 0.f;
    for (int i = threadIdx.x; i < D; i += 256) {
        float v = x[i];
        s += v * v;
    }
#pragma unroll
    for (int o = 16; o; o >>= 1) s += __shfl_xor_sync(0xffffffffu, s, o);
    __shared__ float red[8];
    __shared__ float inv_s;
    if ((threadIdx.x & 31) == 0) red[threadIdx.x >> 5] = s;
    __syncthreads();
    if (threadIdx.x == 0) {
        float tt = 0.f;
#pragma unroll
        for (int i = 0; i < 8; i++) tt += red[i];
        inv_s = rsqrtf(tt / (float)D + 1e-6f);
    }
    __syncthreads();
    const float inv = inv_s;
    const int Dw = D >> 1;
    for (int i = threadIdx.x; i < Dw; i += 256) {
        float a = w[2 * i]     * (x[2 * i]     * inv);
        float b = w[2 * i + 1] * (x[2 * i + 1] * inv);
        uint32_t hi, lo;
        split2(a, b, hi, lo);
        oh[(size_t)row * Dw + i] = hi;
        ol[(size_t)row * Dw + i] = lo;
    }
}

// ---------------------------------------------------------------------------
// 3-term bf16 GEMM, 128x128 tile, ldmatrix, 2-stage cp.async (R11-proven)
// ---------------------------------------------------------------------------
#define GS_STAGE_WORDS 10240
#define GEMM_SMEM_BYTES (2 * GS_STAGE_WORDS * 4)

__global__ void __launch_bounds__(256, 2) gemm_bf16x3_ldsm_kernel(
    float* __restrict__ C,
    const uint32_t* __restrict__ Ah, const uint32_t* __restrict__ Al,
    const uint32_t* __restrict__ Bh, const uint32_t* __restrict__ Bl,
    int M, int N, int K, int ldc)
{
    extern __shared__ uint32_t sw[];
    const int Kw  = K >> 1;
    const int tid = threadIdx.x;
    const int lane = tid & 31;
    const int w   = tid >> 5;
    const int wm  = w >> 2;
    const int wn  = w & 3;
    const int g   = lane >> 2;
    const int t   = lane & 3;
    const int m0  = blockIdx.y * 128;
    const int n0  = blockIdx.x * 128;
    const uint32_t sbase = (uint32_t)__cvta_generic_to_shared(sw);

    const int r0 = tid >> 2,          c0 = (tid & 3) * 4;
    const int r1 = (tid + 256) >> 2,  c1 = ((tid + 256) & 3) * 4;

    const int a_row  = (lane & 7) + ((lane >> 3) & 1) * 8;
    const int a_colw = (lane >> 4) * 4;
    const int b_row  = (lane & 7) + ((lane >> 4) & 1) * 8;
    const int b_colw = ((lane >> 3) & 1) * 4;

    float acc[4][4][4];
#pragma unroll
    for (int mi = 0; mi < 4; mi++)
#pragma unroll
        for (int ni = 0; ni < 4; ni++)
#pragma unroll
            for (int e = 0; e < 4; e++) acc[mi][ni][e] = 0.f;

    const int nchunks = K / 32;

#define LOAD_CHUNK(ch, stage)                                                    \
    do {                                                                         \
        const int kw0 = (ch) * 16;                                               \
        uint32_t sb = sbase + (stage) * (GS_STAGE_WORDS * 4);                    \
        uint32_t d0 = sb + (r0 * 20 + c0) * 4;                                   \
        uint32_t d1 = sb + (r1 * 20 + c1) * 4;                                   \
        CP16(d0,          Ah + (size_t)(m0 + r0) * Kw + kw0 + c0);               \
        CP16(d1,          Ah + (size_t)(m0 + r1) * Kw + kw0 + c1);               \
        CP16(d0 + 10240,  Al + (size_t)(m0 + r0) * Kw + kw0 + c0);               \
        CP16(d1 + 10240,  Al + (size_t)(m0 + r1) * Kw + kw0 + c1);               \
        CP16(d0 + 20480,  Bh + (size_t)(n0 + r0) * Kw + kw0 + c0);               \
        CP16(d1 + 20480,  Bh + (size_t)(n0 + r1) * Kw + kw0 + c1);               \
        CP16(d0 + 30720,  Bl + (size_t)(n0 + r0) * Kw + kw0 + c0);               \
        CP16(d1 + 30720,  Bl + (size_t)(n0 + r1) * Kw + kw0 + c1);               \
    } while (0)

    LOAD_CHUNK(0, 0);
    CP_COMMIT();

    for (int ch = 0; ch < nchunks; ch++) {
        if (ch + 1 < nchunks) {
            LOAD_CHUNK(ch + 1, (ch + 1) & 1);
            CP_COMMIT();
            asm volatile("cp.async.wait_group 1;");
        } else {
            asm volatile("cp.async.wait_group 0;");
        }
        __syncthreads();

        uint32_t sAh = sbase + (ch & 1) * (GS_STAGE_WORDS * 4);
        uint32_t sAl = sAh + 2560 * 4;
        uint32_t sBh = sAh + 5120 * 4;
        uint32_t sBl = sAh + 7680 * 4;

#pragma unroll
        for (int kk = 0; kk < 2; kk++) {
            uint32_t bhq[2][4], blq[2][4];
#pragma unroll
            for (int p = 0; p < 2; p++) {
                uint32_t boff = ((wn * 32 + p * 16 + b_row) * 20
                                 + kk * 8 + b_colw) * 4;
                ldsm_x4(bhq[p], sBh + boff);
                ldsm_x4(blq[p], sBl + boff);
            }
#pragma unroll
            for (int mi = 0; mi < 4; mi++) {
                uint32_t aoff = ((wm * 64 + mi * 16 + a_row) * 20
                                 + kk * 8 + a_colw) * 4;
                uint32_t ah[4], al[4];
                ldsm_x4(ah, sAh + aoff);
                ldsm_x4(al, sAl + aoff);
#pragma unroll
                for (int ni = 0; ni < 4; ni++) {
                    const uint32_t* bh = &bhq[ni >> 1][(ni & 1) * 2];
                    const uint32_t* bl = &blq[ni >> 1][(ni & 1) * 2];
                    mma_bf16(acc[mi][ni], ah, bh);
                    mma_bf16(acc[mi][ni], al, bh);
                    mma_bf16(acc[mi][ni], ah, bl);
                }
            }
        }
        __syncthreads();
    }
#undef LOAD_CHUNK

#pragma unroll
    for (int mi = 0; mi < 4; mi++) {
        int rr0 = m0 + wm * 64 + mi * 16 + g;
        int rr1 = rr0 + 8;
#pragma unroll
        for (int ni = 0; ni < 4; ni++) {
            int c = n0 + wn * 32 + ni * 8 + 2 * t;
            if (c < N) {
                *(float2*)(C + (size_t)rr0 * ldc + c) =
                    make_float2(acc[mi][ni][0], acc[mi][ni][1]);
                *(float2*)(C + (size_t)rr1 * ldc + c) =
                    make_float2(acc[mi][ni][2], acc[mi][ni][3]);
            }
        }
    }
}

// ---------------------------------------------------------------------------
// RoPE (deinterleave + rotate_half fused); k_pe read from combined buffer
// ---------------------------------------------------------------------------
__global__ void rope_kernel(float* __restrict__ q, float* __restrict__ kpe,
                            const float* __restrict__ kpe_src, int ld_src,
                            const int* __restrict__ pos_ids)
{
    const int srow = blockIdx.x;
    const int tid  = threadIdx.x;
    const int j    = tid & 31;

    const float pos  = (float)pos_ids[srow];
    const float freq = __expf(-((2.f * (float)j) / 64.f) * logf(10000.f));
    const float ang  = pos * freq;
    float cv, sv;
    __sincosf(ang, &sv, &cv);

    if (tid < NH * 32) {
        const int h = tid >> 5;
        float* base = q + (size_t)srow * (NH * QHD) + h * QHD + NOPE;
        float x0 = base[2 * j];
        float x1 = base[2 * j + 1];
        __syncwarp();
        base[j]      = x0 * cv - x1 * sv;
        base[32 + j] = x1 * cv + x0 * sv;
    } else {
        const float* src = kpe_src + (size_t)srow * ld_src;
        float x0 = src[2 * j];
        float x1 = src[2 * j + 1];
        float* dst = kpe + (size_t)srow * ROPE_D;
        dst[j]      = x0 * cv - x1 * sv;
        dst[32 + j] = x1 * cv + x0 * sv;
    }
}

// ---------------------------------------------------------------------------
// Pack Q and K per head into hi/lo word arrays [h][s][96w]
// ---------------------------------------------------------------------------
__global__ void qk_pack_kernel(
    uint32_t* __restrict__ qh, uint32_t* __restrict__ ql,
    uint32_t* __restrict__ kh, uint32_t* __restrict__ kl,
    const float* __restrict__ q, const float* __restrict__ kv,
    const float* __restrict__ kpe)
{
    int idx = blockIdx.x * 256 + threadIdx.x;
    if (idx >= NH * S_LEN * 96) return;
    int w = idx % 96;
    int s = (idx / 96) % S_LEN;
    int h = idx / (96 * S_LEN);

    uint32_t hi, lo;
    const float* qp = q + (size_t)s * (NH * QHD) + h * QHD + 2 * w;
    split2(qp[0], qp[1], hi, lo);
    qh[idx] = hi; ql[idx] = lo;
    float a, b;
    if (w < 64) {
        const float* kp = kv + (size_t)s * (NH * 256) + h * 256 + 2 * w;
        a = kp[0]; b = kp[1];
    } else {
        const float* kp = kpe + (size_t)s * ROPE_D + 2 * (w - 64);
        a = kp[0]; b = kp[1];
    }
    split2(a, b, hi, lo);
    kh[idx] = hi; kl[idx] = lo;
}

// ---------------------------------------------------------------------------
// Pack V transposed: g_kv -> vt [h][vd][s/2 words]
// ---------------------------------------------------------------------------
__global__ void vt_pack_kernel(uint32_t* __restrict__ vth, uint32_t* __restrict__ vtl,
                               const float* __restrict__ kv)
{
    __shared__ float tile[64][33];
    const int s0 = blockIdx.x * 64, v0 = blockIdx.y * 32, h = blockIdx.z;
    const int tid = threadIdx.x;
#pragma unroll
    for (int i = 0; i < 8; i++) {
        int e = tid + i * 256;
        int s = e >> 5, vd = e & 31;
        tile[s][vd] = kv[(size_t)(s0 + s) * (NH * 256) + h * 256 + NOPE + v0 + vd];
    }
    __syncthreads();
#pragma unroll
    for (int i = 0; i < 4; i++) {
        int e = tid + i * 256;
        int vd = e >> 5, sw_ = e & 31;
        uint32_t hi, lo;
        split2(tile[2 * sw_][vd], tile[2 * sw_ + 1][vd], hi, lo);
        size_t o = (size_t)(h * VD + v0 + vd) * (S_LEN / 2) + (s0 >> 1) + sw_;
        vth[o] = hi; vtl[o] = lo;
    }
}

// ---------------------------------------------------------------------------
// Tensor-core causal flash attention (3-term bf16, fp32 softmax/acc).
// ---------------------------------------------------------------------------
#define FLASH_SMEM_BYTES (52480 * 4)

__global__ void __launch_bounds__(256, 1) flash_mma_kernel(
    uint32_t* __restrict__ Oh, uint32_t* __restrict__ Ol,
    const uint32_t* __restrict__ Qh, const uint32_t* __restrict__ Ql,
    const uint32_t* __restrict__ Kh, const uint32_t* __restrict__ Kl,
    const uint32_t* __restrict__ Vh, const uint32_t* __restrict__ Vl)
{
    extern __shared__ uint32_t sw[];
    uint32_t* sQh = sw;
    uint32_t* sQl = sw + 6400;
    uint32_t* sKh = sw + 12800;
    uint32_t* sKl = sw + 25600;
    uint32_t* sVh = sw + 38400;
    uint32_t* sVl = sw + 43008;
    uint32_t* sPh = sw + 47616;
    uint32_t* sPl = sw + 49920;
    float*    sMax = (float*)(sw + 52224);
    float*    sSum = sMax + 128;

    const int tid  = threadIdx.x;
    const int lane = tid & 31;
    const int w    = tid >> 5;
    const int wm   = w & 3;
    const int wn   = w >> 2;
    const int g    = lane >> 2;
    const int t    = lane & 3;
    const int h    = blockIdx.y;
    const int qb   = blockIdx.x;
    const int q0   = qb * 64;
    const uint32_t sb = (uint32_t)__cvta_generic_to_shared(sw);

    const uint32_t* Qhp = Qh + ((size_t)h * S_LEN + q0) * 96;
    const uint32_t* Qlp = Ql + ((size_t)h * S_LEN + q0) * 96;
    const uint32_t* Khp = Kh + (size_t)h * S_LEN * 96;
    const uint32_t* Klp = Kl + (size_t)h * S_LEN * 96;
    const uint32_t* Vhp = Vh + (size_t)h * VD * (S_LEN / 2);
    const uint32_t* Vlp = Vl + (size_t)h * VD * (S_LEN / 2);

#pragma unroll
    for (int i = 0; i < 6; i++) {
        int c = tid + i * 256;
        int r = c / 24, c4 = (c % 24) * 4;
        CP16(sb + (r * 100 + c4) * 4,           Qhp + r * 96 + c4);
        CP16(sb + (6400 + r * 100 + c4) * 4,    Qlp + r * 96 + c4);
        CP16(sb + (12800 + r * 100 + c4) * 4,   Khp + r * 96 + c4);
        CP16(sb + (25600 + r * 100 + c4) * 4,   Klp + r * 96 + c4);
    }
    CP_COMMIT();

    float oacc[8][4];
#pragma unroll
    for (int ni = 0; ni < 8; ni++)
#pragma unroll
        for (int e = 0; e < 4; e++) oacc[ni][e] = 0.f;
    float mi0 = -1e30f, mi1 = -1e30f, li0 = 0.f, li1 = 0.f;

    const int r0 = wm * 16 + g, r1 = r0 + 8;
    const int qi0 = q0 + r0, qi1 = q0 + r1;
    const float scale = rsqrtf((float)QHD);

    for (int kb = 0; kb <= qb; kb++) {
        const int k0 = kb * 64;
#pragma unroll
        for (int i = 0; i < 4; i++) {
            int c = tid + i * 256;
            int r = c >> 3, c4 = (c & 7) * 4;
            CP16(sb + (38400 + r * 36 + c4) * 4, Vhp + (size_t)r * (S_LEN/2) + (k0 >> 1) + c4);
            CP16(sb + (43008 + r * 36 + c4) * 4, Vlp + (size_t)r * (S_LEN/2) + (k0 >> 1) + c4);
        }
        CP_COMMIT();
        if (kb < qb) {
            const int kn = (kb + 1) * 64;
            const int bo = ((kb + 1) & 1) * 6400;
#pragma unroll
            for (int i = 0; i < 6; i++) {
                int c = tid + i * 256;
                int r = c / 24, c4 = (c % 24) * 4;
                CP16(sb + (12800 + bo + r * 100 + c4) * 4, Khp + (size_t)(kn + r) * 96 + c4);
                CP16(sb + (25600 + bo + r * 100 + c4) * 4, Klp + (size_t)(kn + r) * 96 + c4);
            }
            CP_COMMIT();
            asm volatile("cp.async.wait_group 2;");
        } else {
            asm volatile("cp.async.wait_group 1;");
        }
        __syncthreads();

        const uint32_t* kbh = sKh + (kb & 1) * 6400;
        const uint32_t* kbl = sKl + (kb & 1) * 6400;
        float sacc[4][4];
#pragma unroll
        for (int ni = 0; ni < 4; ni++)
#pragma unroll
            for (int e = 0; e < 4; e++) sacc[ni][e] = 0.f;

#pragma unroll
        for (int ka = 0; ka < 12; ka++) {
            uint32_t bh[4][2], bl[4][2];
#pragma unroll
            for (int ni = 0; ni < 4; ni++) {
                int ba = (wn * 32 + ni * 8 + g) * 100 + ka * 8 + t;
                bh[ni][0] = kbh[ba]; bh[ni][1] = kbh[ba + 4];
                bl[ni][0] = kbl[ba]; bl[ni][1] = kbl[ba + 4];
            }
            int aa = r0 * 100 + ka * 8 + t;
            uint32_t ah[4], al[4];
            ah[0] = sQh[aa]; ah[1] = sQh[aa + 800]; ah[2] = sQh[aa + 4]; ah[3] = sQh[aa + 804];
            al[0] = sQl[aa]; al[1] = sQl[aa + 800]; al[2] = sQl[aa + 4]; al[3] = sQl[aa + 804];
#pragma unroll
            for (int ni = 0; ni < 4; ni++) {
                mma_bf16(sacc[ni], ah, bh[ni]);
                mma_bf16(sacc[ni], al, bh[ni]);
                mma_bf16(sacc[ni], ah, bl[ni]);
            }
        }

        const bool diag = (kb == qb);
        float v0[8], v1[8];
        float rm0 = -1e30f, rm1 = -1e30f;
#pragma unroll
        for (int ni = 0; ni < 4; ni++) {
#pragma unroll
            for (int e = 0; e < 2; e++) {
                int col = k0 + wn * 32 + ni * 8 + 2 * t + e;
                float x0 = sacc[ni][e]     * scale;
                float x1 = sacc[ni][2 + e] * scale;
                if (diag && col > qi0) x0 = -1e30f;
                if (diag && col > qi1) x1 = -1e30f;
                v0[ni * 2 + e] = x0;
                v1[ni * 2 + e] = x1;
                rm0 = fmaxf(rm0, x0);
                rm1 = fmaxf(rm1, x1);
            }
        }
        rm0 = fmaxf(rm0, __shfl_xor_sync(0xffffffffu, rm0, 1));
        rm0 = fmaxf(rm0, __shfl_xor_sync(0xffffffffu, rm0, 2));
        rm1 = fmaxf(rm1, __shfl_xor_sync(0xffffffffu, rm1, 1));
        rm1 = fmaxf(rm1, __shfl_xor_sync(0xffffffffu, rm1, 2));
        if (t == 0) {
            sMax[r0 * 2 + wn] = rm0;
            sMax[r1 * 2 + wn] = rm1;
        }
        __syncthreads();
        float mn0 = fmaxf(mi0, fmaxf(sMax[r0 * 2], sMax[r0 * 2 + 1]));
        float mn1 = fmaxf(mi1, fmaxf(sMax[r1 * 2], sMax[r1 * 2 + 1]));
        float al0 = __expf(mi0 - mn0);
        float al1 = __expf(mi1 - mn1);
        float ls0 = 0.f, ls1 = 0.f;
#pragma unroll
        for (int i = 0; i < 8; i++) {
            v0[i] = __expf(v0[i] - mn0); ls0 += v0[i];
            v1[i] = __expf(v1[i] - mn1); ls1 += v1[i];
        }
#pragma unroll
        for (int ni = 0; ni < 4; ni++) {
            uint32_t hi, lo;
            split2(v0[ni * 2], v0[ni * 2 + 1], hi, lo);
            sPh[r0 * 36 + wn * 16 + ni * 4 + t] = hi;
            sPl[r0 * 36 + wn * 16 + ni * 4 + t] = lo;
            split2(v1[ni * 2], v1[ni * 2 + 1], hi, lo);
            sPh[r1 * 36 + wn * 16 + ni * 4 + t] = hi;
            sPl[r1 * 36 + wn * 16 + ni * 4 + t] = lo;
        }
        ls0 += __shfl_xor_sync(0xffffffffu, ls0, 1);
        ls0 += __shfl_xor_sync(0xffffffffu, ls0, 2);
        ls1 += __shfl_xor_sync(0xffffffffu, ls1, 1);
        ls1 += __shfl_xor_sync(0xffffffffu, ls1, 2);
        if (t == 0) {
            sSum[r0 * 2 + wn] = ls0;
            sSum[r1 * 2 + wn] = ls1;
        }
        __syncthreads();
        li0 = li0 * al0 + sSum[r0 * 2] + sSum[r0 * 2 + 1];
        li1 = li1 * al1 + sSum[r1 * 2] + sSum[r1 * 2 + 1];
        mi0 = mn0; mi1 = mn1;
#pragma unroll
        for (int ni = 0; ni < 8; ni++) {
            oacc[ni][0] *= al0; oacc[ni][1] *= al0;
            oacc[ni][2] *= al1; oacc[ni][3] *= al1;
        }
        if (kb < qb) asm volatile("cp.async.wait_group 1;");
        else         asm volatile("cp.async.wait_group 0;");
        __syncthreads();

#pragma unroll
        for (int ka = 0; ka < 4; ka++) {
            int aa = r0 * 36 + ka * 8 + t;
            uint32_t ah[4], al[4];
            ah[0] = sPh[aa]; ah[1] = sPh[aa + 288]; ah[2] = sPh[aa + 4]; ah[3] = sPh[aa + 292];
            al[0] = sPl[aa]; al[1] = sPl[aa + 288]; al[2] = sPl[aa + 4]; al[3] = sPl[aa + 292];
#pragma unroll
            for (int ni = 0; ni < 8; ni++) {
                int ba = (wn * 64 + ni * 8 + g) * 36 + ka * 8 + t;
                uint32_t bh[2], bl[2];
                bh[0] = sVh[ba]; bh[1] = sVh[ba + 4];
                bl[0] = sVl[ba]; bl[1] = sVl[ba + 4];
                mma_bf16(oacc[ni], ah, bh);
                mma_bf16(oacc[ni], al, bh);
                mma_bf16(oacc[ni], ah, bl);
            }
        }
        __syncthreads();
    }

    float inv0 = 1.f / li0, inv1 = 1.f / li1;
#pragma unroll
    for (int ni = 0; ni < 8; ni++) {
        int col  = h * VD + wn * 64 + ni * 8 + 2 * t;
        int word = col >> 1;
        uint32_t hi, lo;
        split2(oacc[ni][0] * inv0, oacc[ni][1] * inv0, hi, lo);
        Oh[(size_t)(q0 + r0) * (NH * VD / 2) + word] = hi;
        Ol[(size_t)(q0 + r0) * (NH * VD / 2) + word] = lo;
        split2(oacc[ni][2] * inv1, oacc[ni][3] * inv1, hi, lo);
        Oh[(size_t)(q0 + r1) * (NH * VD / 2) + word] = hi;
        Ol[(size_t)(q0 + r1) * (NH * VD / 2) + word] = lo;
    }
}

// ---------------------------------------------------------------------------
// Launch
// ---------------------------------------------------------------------------
extern "C" void kernel_launch(void* const* d_in, const int* in_sizes, int n_in,
                              void* d_out, int out_size)
{
    const float* hidden = (const float*)d_in[0];
    const int*   pos    = (const int*)d_in[1];
    const float* Wqa    = (const float*)d_in[2];
    const float* qa_ln  = (const float*)d_in[3];
    const float* Wqb    = (const float*)d_in[4];
    const float* Wkva   = (const float*)d_in[5];
    const float* kv_ln  = (const float*)d_in[6];
    const float* Wkvb   = (const float*)d_in[7];
    const float* Wo     = (const float*)d_in[8];
    float* out = (float*)d_out;

    float *qackv, *q, *kpe, *kv;
    cudaGetSymbolAddress((void**)&qackv, g_qackv);
    cudaGetSymbolAddress((void**)&q,     g_q);
    cudaGetSymbolAddress((void**)&kpe,   g_kpe);
    cudaGetSymbolAddress((void**)&kv,    g_kv);

    uint32_t *hidh, *hidl, *qanh, *qanl, *ckvnh, *ckvnl, *attnh, *attnl;
    uint32_t *W12th, *W12tl, *Wqbth, *Wqbtl, *Wkvbth, *Wkvbtl, *Woth, *Wotl;
    uint32_t *qph, *qpl, *kph, *kpl, *vth, *vtl;
    cudaGetSymbolAddress((void**)&hidh,  g_hidh);
    cudaGetSymbolAddress((void**)&hidl,  g_hidl);
    cudaGetSymbolAddress((void**)&qanh,  g_qanh);
    cudaGetSymbolAddress((void**)&qanl,  g_qanl);
    cudaGetSymbolAddress((void**)&ckvnh, g_ckvnh);
    cudaGetSymbolAddress((void**)&ckvnl, g_ckvnl);
    cudaGetSymbolAddress((void**)&attnh, g_attnh);
    cudaGetSymbolAddress((void**)&attnl, g_attnl);
    cudaGetSymbolAddress((void**)&W12th,  g_W12th);
    cudaGetSymbolAddress((void**)&W12tl,  g_W12tl);
    cudaGetSymbolAddress((void**)&Wqbth,  g_Wqbth);
    cudaGetSymbolAddress((void**)&Wqbtl,  g_Wqbtl);
    cudaGetSymbolAddress((void**)&Wkvbth, g_Wkvbth);
    cudaGetSymbolAddress((void**)&Wkvbtl, g_Wkvbtl);
    cudaGetSymbolAddress((void**)&Woth,   g_Woth);
    cudaGetSymbolAddress((void**)&Wotl,   g_Wotl);
    cudaGetSymbolAddress((void**)&qph, g_qph);
    cudaGetSymbolAddress((void**)&qpl, g_qpl);
    cudaGetSymbolAddress((void**)&kph, g_kph);
    cudaGetSymbolAddress((void**)&kpl, g_kpl);
    cudaGetSymbolAddress((void**)&vth, g_vth);
    cudaGetSymbolAddress((void**)&vtl, g_vtl);

    cudaFuncSetAttribute(gemm_bf16x3_ldsm_kernel,
                         cudaFuncAttributeMaxDynamicSharedMemorySize, GEMM_SMEM_BYTES);
    cudaFuncSetAttribute(flash_mma_kernel,
                         cudaFuncAttributeMaxDynamicSharedMemorySize, FLASH_SMEM_BYTES);

    // ---- batched weight transpose+split (1 launch, 5 jobs) ----
    WtJobs jobs;
    // Wqa: rows 0..1535 of combined
    jobs.j[0] = { Wqa,  W12th,               W12tl,               HID,  QLR,          48,  0 };
    // Wkva: rows 1536..2175 of combined
    jobs.j[1] = { Wkva, W12th + 1536*(HID/2), W12tl + 1536*(HID/2), HID, CKVD,        20,  3072 };
    jobs.j[2] = { Wqb,  Wqbth,               Wqbtl,               QLR,  NH * QHD,     96,  4352 };
    jobs.j[3] = { Wkvb, Wkvbth,              Wkvbtl,              KVLR, NH*(NOPE+VD), 128, 8960 };
    jobs.j[4] = { Wo,   Woth,                Wotl,                NH*VD, HID,         64,  11008 };
    jobs.total = 15104;
    wt_split_all_kernel<<<jobs.total, dim3(32, 8)>>>(jobs);

    split_pack_kernel<<<(S_LEN * (HID/2) + 255) / 256, 256>>>(hidh, hidl, hidden, S_LEN * (HID/2));

    // 1+2) [qa | ckv] = hidden @ [Wqa | Wkva]   (grid 17x16 = 272 CTAs)
    gemm_bf16x3_ldsm_kernel<<<dim3(NC12 / 128, S_LEN / 128), 256, GEMM_SMEM_BYTES>>>(
        qackv, hidh, hidl, W12th, W12tl, S_LEN, NC12V, HID, NC12);
    // 3-4) rmsnorms -> packed (from combined buffer)
    rmsnorm_pack_kernel<<<S_LEN, 256>>>(qanh, qanl, qackv, qa_ln, QLR, NC12);
    rmsnorm_pack_kernel<<<S_LEN, 256>>>(ckvnh, ckvnl, qackv + QLR, kv_ln, KVLR, NC12);
    // 5) q = q_a_n @ Wqb
    gemm_bf16x3_ldsm_kernel<<<dim3(3072 / 128, S_LEN / 128), 256, GEMM_SMEM_BYTES>>>(
        q, qanh, qanl, Wqbth, Wqbtl, S_LEN, NH * QHD, QLR, NH * QHD);
    // 6) kv = ckv_n @ Wkvb
    gemm_bf16x3_ldsm_kernel<<<dim3(4096 / 128, S_LEN / 128), 256, GEMM_SMEM_BYTES>>>(
        kv, ckvnh, ckvnl, Wkvbth, Wkvbtl, S_LEN, NH * 256, KVLR, NH * 256);
    // 7) RoPE (k_pe from combined buffer cols [2048, 2112))
    rope_kernel<<<S_LEN, (NH + 1) * 32>>>(q, kpe, qackv + QLR + KVLR, NC12, pos);
    // 8) pack flash inputs
    qk_pack_kernel<<<(NH * S_LEN * 96 + 255) / 256, 256>>>(qph, qpl, kph, kpl, q, kv, kpe);
    vt_pack_kernel<<<dim3(S_LEN / 64, VD / 32, NH), 256>>>(vth, vtl, kv);
    // 9) tensor-core flash attention
    flash_mma_kernel<<<dim3(S_LEN / 64, NH), 256, FLASH_SMEM_BYTES>>>(
        attnh, attnl, qph, qpl, kph, kpl, vth, vtl);
    // 10) out = attn @ Wo
    gemm_bf16x3_ldsm_kernel<<<dim3(HID / 128, S_LEN / 128), 256, GEMM_SMEM_BYTES>>>(
        out, attnh, attnl, Woth, Wotl, S_LEN, HID, NH * VD, HID);
}

// round 15
// speedup vs baseline: 1.1625x; 1.0011x over previous
#include <cuda_runtime.h>
#include <cuda_bf16.h>
#include <math.h>
#include <stdint.h>

// ---------------------------------------------------------------------------
// Problem constants (DeepseekV3 MLA prefill, B=1, S=2048)
// ---------------------------------------------------------------------------
#define S_LEN  2048
#define HID    2048
#define NH     16
#define NOPE   128
#define ROPE_D 64
#define QHD    192
#define VD     128
#define QLR    1536
#define KVLR   512
#define CKVD   576
#define NC12   2176   // combined GEMM1+2 output width (1536 + 640 pad)
#define NC12V  2112   // valid cols (1536 + 576)

// ---------------------------------------------------------------------------
// Scratch (static __device__ arrays — no runtime allocation)
// ---------------------------------------------------------------------------
__device__ float g_qackv[S_LEN * NC12];          // [qa | ckv] fp32
__device__ float g_q   [S_LEN * NH * QHD];
__device__ float g_kpe [S_LEN * ROPE_D];
__device__ float g_kv  [S_LEN * NH * (NOPE + VD)];

// Packed bf16 hi/lo activations
__device__ uint32_t g_hidh [S_LEN * (HID/2)];
__device__ uint32_t g_hidl [S_LEN * (HID/2)];
__device__ uint32_t g_qanh [S_LEN * (QLR/2)];
__device__ uint32_t g_qanl [S_LEN * (QLR/2)];
__device__ uint32_t g_ckvnh[S_LEN * (KVLR/2)];
__device__ uint32_t g_ckvnl[S_LEN * (KVLR/2)];
__device__ uint32_t g_attnh[S_LEN * (NH*VD/2)];
__device__ uint32_t g_attnl[S_LEN * (NH*VD/2)];

// Transposed + split weights: [Npad][K/2] words
__device__ uint32_t g_W12th [NC12 * (HID/2)];    // Wqa rows 0..1535, Wkva rows 1536..2175
__device__ uint32_t g_W12tl [NC12 * (HID/2)];
__device__ uint32_t g_Wqbth [3072 * (QLR/2)];
__device__ uint32_t g_Wqbtl [3072 * (QLR/2)];
__device__ uint32_t g_Wkvbth[4096 * (KVLR/2)];
__device__ uint32_t g_Wkvbtl[4096 * (KVLR/2)];
__device__ uint32_t g_Woth  [2048 * (NH*VD/2)];
__device__ uint32_t g_Wotl  [2048 * (NH*VD/2)];

// Packed per-head flash inputs
__device__ uint32_t g_qph[NH * S_LEN * 96];
__device__ uint32_t g_qpl[NH * S_LEN * 96];
__device__ uint32_t g_kph[NH * S_LEN * 96];
__device__ uint32_t g_kpl[NH * S_LEN * 96];
__device__ uint32_t g_vth[NH * VD * (S_LEN/2)];
__device__ uint32_t g_vtl[NH * VD * (S_LEN/2)];

// ---------------------------------------------------------------------------
// Helpers
// ---------------------------------------------------------------------------
__device__ __forceinline__ void split2(float a, float b, uint32_t& hi, uint32_t& lo) {
    __nv_bfloat16 ah = __float2bfloat16(a);
    __nv_bfloat16 bh = __float2bfloat16(b);
    __nv_bfloat16 al = __float2bfloat16(a - __bfloat162float(ah));
    __nv_bfloat16 bl = __float2bfloat16(b - __bfloat162float(bh));
    hi = (uint32_t)__bfloat16_as_ushort(ah) | ((uint32_t)__bfloat16_as_ushort(bh) << 16);
    lo = (uint32_t)__bfloat16_as_ushort(al) | ((uint32_t)__bfloat16_as_ushort(bl) << 16);
}

__device__ __forceinline__ void mma_bf16(float c[4], const uint32_t a[4],
                                         const uint32_t b[2]) {
    asm volatile(
        "mma.sync.aligned.m16n8k16.row.col.f32.bf16.bf16.f32 "
        "{%0,%1,%2,%3}, {%4,%5,%6,%7}, {%8,%9}, {%0,%1,%2,%3};"
        : "+f"(c[0]), "+f"(c[1]), "+f"(c[2]), "+f"(c[3])
        : "r"(a[0]), "r"(a[1]), "r"(a[2]), "r"(a[3]), "r"(b[0]), "r"(b[1]));
}

__device__ __forceinline__ void ldsm_x4(uint32_t r[4], uint32_t addr) {
    asm volatile("ldmatrix.sync.aligned.m8n8.x4.shared.b16 {%0,%1,%2,%3}, [%4];"
        : "=r"(r[0]), "=r"(r[1]), "=r"(r[2]), "=r"(r[3]) : "r"(addr));
}

#define CP16(dst, src) \
    asm volatile("cp.async.cg.shared.global [%0], [%1], 16;" :: "r"(dst), "l"(src))
#define CP_COMMIT() asm volatile("cp.async.commit_group;")

// ---------------------------------------------------------------------------
// Batched weight transpose + split: 5 jobs in one launch.
// Each job: W[K][N] -> Th/Tl[Npad][K/2] words (Th/Tl may be row-offset).
// ---------------------------------------------------------------------------
struct WtJob {
    const float* W;
    uint32_t* Th;
    uint32_t* Tl;
    int K;       // rows of W (inner dim)
    int N;       // valid cols of W
    int nbx;     // Npad/32
    int blk0;    // first flat block id
};
struct WtJobs { WtJob j[5]; int total; };

__global__ void __launch_bounds__(256) wt_split_all_kernel(WtJobs jobs)
{
    __shared__ float t[32][33];
    const int bid = blockIdx.x;
    int ji = 0;
#pragma unroll
    for (int i = 1; i < 5; i++)
        if (bid >= jobs.j[i].blk0) ji = i;
    const WtJob& J = jobs.j[ji];
    const int loc = bid - J.blk0;
    const int n0 = (loc % J.nbx) * 32;
    const int k0 = (loc / J.nbx) * 32;

    const int tx = threadIdx.x, ty = threadIdx.y;
    const int n = n0 + tx;
#pragma unroll
    for (int i = 0; i < 4; i++) {
        int k = ty + i * 8;
        t[k][tx] = (n < J.N) ? J.W[(size_t)(k0 + k) * J.N + n] : 0.f;
    }
    __syncthreads();
    const int Kw = J.K >> 1;
#pragma unroll
    for (int it = 0; it < 2; it++) {
        int s  = ty * 32 + tx + it * 256;
        int nl = s >> 4, wd = s & 15;
        uint32_t hi, lo;
        split2(t[2 * wd][nl], t[2 * wd + 1][nl], hi, lo);
        size_t o = (size_t)(n0 + nl) * Kw + (k0 >> 1) + wd;
        J.Th[o] = hi;
        J.Tl[o] = lo;
    }
}

// ---------------------------------------------------------------------------
// Activation split
// ---------------------------------------------------------------------------
__global__ void split_pack_kernel(uint32_t* __restrict__ oh, uint32_t* __restrict__ ol,
                                  const float* __restrict__ x, int nWords)
{
    int i = blockIdx.x * 256 + threadIdx.x;
    if (i < nWords) {
        float2 v = ((const float2*)x)[i];
        uint32_t hi, lo;
        split2(v.x, v.y, hi, lo);
        oh[i] = hi;
        ol[i] = lo;
    }
}

// ---------------------------------------------------------------------------
// RMSNorm fused with hi/lo pack
// ---------------------------------------------------------------------------
__global__ void __launch_bounds__(256) rmsnorm_pack_kernel(
    uint32_t* __restrict__ oh, uint32_t* __restrict__ ol,
    const float* __restrict__ in, const float* __restrict__ w, int D, int ldin)
{
    const int row = blockIdx.x;
    const float* x = in + (size_t)row * ldin;

    float s = 0.f;
    for (int i = threadIdx.x; i < D; i += 256) {
        float v = x[i];
        s += v * v;
    }
#pragma unroll
    for (int o = 16; o; o >>= 1) s += __shfl_xor_sync(0xffffffffu, s, o);
    __shared__ float red[8];
    __shared__ float inv_s;
    if ((threadIdx.x & 31) == 0) red[threadIdx.x >> 5] = s;
    __syncthreads();
    if (threadIdx.x == 0) {
        float tt = 0.f;
#pragma unroll
        for (int i = 0; i < 8; i++) tt += red[i];
        inv_s = rsqrtf(tt / (float)D + 1e-6f);
    }
    __syncthreads();
    const float inv = inv_s;
    const int Dw = D >> 1;
    for (int i = threadIdx.x; i < Dw; i += 256) {
        float a = w[2 * i]     * (x[2 * i]     * inv);
        float b = w[2 * i + 1] * (x[2 * i + 1] * inv);
        uint32_t hi, lo;
        split2(a, b, hi, lo);
        oh[(size_t)row * Dw + i] = hi;
        ol[(size_t)row * Dw + i] = lo;
    }
}

// ---------------------------------------------------------------------------
// 3-term bf16 GEMM, 128x128 tile, ldmatrix, 2-stage cp.async (R11-proven)
// ---------------------------------------------------------------------------
#define GS_STAGE_WORDS 10240
#define GEMM_SMEM_BYTES (2 * GS_STAGE_WORDS * 4)

__global__ void __launch_bounds__(256, 2) gemm_bf16x3_ldsm_kernel(
    float* __restrict__ C,
    const uint32_t* __restrict__ Ah, const uint32_t* __restrict__ Al,
    const uint32_t* __restrict__ Bh, const uint32_t* __restrict__ Bl,
    int M, int N, int K, int ldc)
{
    extern __shared__ uint32_t sw[];
    const int Kw  = K >> 1;
    const int tid = threadIdx.x;
    const int lane = tid & 31;
    const int w   = tid >> 5;
    const int wm  = w >> 2;
    const int wn  = w & 3;
    const int g   = lane >> 2;
    const int t   = lane & 3;
    const int m0  = blockIdx.y * 128;
    const int n0  = blockIdx.x * 128;
    const uint32_t sbase = (uint32_t)__cvta_generic_to_shared(sw);

    const int r0 = tid >> 2,          c0 = (tid & 3) * 4;
    const int r1 = (tid + 256) >> 2,  c1 = ((tid + 256) & 3) * 4;

    const int a_row  = (lane & 7) + ((lane >> 3) & 1) * 8;
    const int a_colw = (lane >> 4) * 4;
    const int b_row  = (lane & 7) + ((lane >> 4) & 1) * 8;
    const int b_colw = ((lane >> 3) & 1) * 4;

    float acc[4][4][4];
#pragma unroll
    for (int mi = 0; mi < 4; mi++)
#pragma unroll
        for (int ni = 0; ni < 4; ni++)
#pragma unroll
            for (int e = 0; e < 4; e++) acc[mi][ni][e] = 0.f;

    const int nchunks = K / 32;

#define LOAD_CHUNK(ch, stage)                                                    \
    do {                                                                         \
        const int kw0 = (ch) * 16;                                               \
        uint32_t sb = sbase + (stage) * (GS_STAGE_WORDS * 4);                    \
        uint32_t d0 = sb + (r0 * 20 + c0) * 4;                                   \
        uint32_t d1 = sb + (r1 * 20 + c1) * 4;                                   \
        CP16(d0,          Ah + (size_t)(m0 + r0) * Kw + kw0 + c0);               \
        CP16(d1,          Ah + (size_t)(m0 + r1) * Kw + kw0 + c1);               \
        CP16(d0 + 10240,  Al + (size_t)(m0 + r0) * Kw + kw0 + c0);               \
        CP16(d1 + 10240,  Al + (size_t)(m0 + r1) * Kw + kw0 + c1);               \
        CP16(d0 + 20480,  Bh + (size_t)(n0 + r0) * Kw + kw0 + c0);               \
        CP16(d1 + 20480,  Bh + (size_t)(n0 + r1) * Kw + kw0 + c1);               \
        CP16(d0 + 30720,  Bl + (size_t)(n0 + r0) * Kw + kw0 + c0);               \
        CP16(d1 + 30720,  Bl + (size_t)(n0 + r1) * Kw + kw0 + c1);               \
    } while (0)

    LOAD_CHUNK(0, 0);
    CP_COMMIT();

    for (int ch = 0; ch < nchunks; ch++) {
        if (ch + 1 < nchunks) {
            LOAD_CHUNK(ch + 1, (ch + 1) & 1);
            CP_COMMIT();
            asm volatile("cp.async.wait_group 1;");
        } else {
            asm volatile("cp.async.wait_group 0;");
        }
        __syncthreads();

        uint32_t sAh = sbase + (ch & 1) * (GS_STAGE_WORDS * 4);
        uint32_t sAl = sAh + 2560 * 4;
        uint32_t sBh = sAh + 5120 * 4;
        uint32_t sBl = sAh + 7680 * 4;

#pragma unroll
        for (int kk = 0; kk < 2; kk++) {
            uint32_t bhq[2][4], blq[2][4];
#pragma unroll
            for (int p = 0; p < 2; p++) {
                uint32_t boff = ((wn * 32 + p * 16 + b_row) * 20
                                 + kk * 8 + b_colw) * 4;
                ldsm_x4(bhq[p], sBh + boff);
                ldsm_x4(blq[p], sBl + boff);
            }
#pragma unroll
            for (int mi = 0; mi < 4; mi++) {
                uint32_t aoff = ((wm * 64 + mi * 16 + a_row) * 20
                                 + kk * 8 + a_colw) * 4;
                uint32_t ah[4], al[4];
                ldsm_x4(ah, sAh + aoff);
                ldsm_x4(al, sAl + aoff);
#pragma unroll
                for (int ni = 0; ni < 4; ni++) {
                    const uint32_t* bh = &bhq[ni >> 1][(ni & 1) * 2];
                    const uint32_t* bl = &blq[ni >> 1][(ni & 1) * 2];
                    mma_bf16(acc[mi][ni], ah, bh);
                    mma_bf16(acc[mi][ni], al, bh);
                    mma_bf16(acc[mi][ni], ah, bl);
                }
            }
        }
        __syncthreads();
    }
#undef LOAD_CHUNK

#pragma unroll
    for (int mi = 0; mi < 4; mi++) {
        int rr0 = m0 + wm * 64 + mi * 16 + g;
        int rr1 = rr0 + 8;
#pragma unroll
        for (int ni = 0; ni < 4; ni++) {
            int c = n0 + wn * 32 + ni * 8 + 2 * t;
            if (c < N) {
                *(float2*)(C + (size_t)rr0 * ldc + c) =
                    make_float2(acc[mi][ni][0], acc[mi][ni][1]);
                *(float2*)(C + (size_t)rr1 * ldc + c) =
                    make_float2(acc[mi][ni][2], acc[mi][ni][3]);
            }
        }
    }
}

// ---------------------------------------------------------------------------
// RoPE (deinterleave + rotate_half fused); k_pe read from combined buffer
// ---------------------------------------------------------------------------
__global__ void rope_kernel(float* __restrict__ q, float* __restrict__ kpe,
                            const float* __restrict__ kpe_src, int ld_src,
                            const int* __restrict__ pos_ids)
{
    const int srow = blockIdx.x;
    const int tid  = threadIdx.x;
    const int j    = tid & 31;

    const float pos  = (float)pos_ids[srow];
    const float freq = __expf(-((2.f * (float)j) / 64.f) * logf(10000.f));
    const float ang  = pos * freq;
    float cv, sv;
    __sincosf(ang, &sv, &cv);

    if (tid < NH * 32) {
        const int h = tid >> 5;
        float* base = q + (size_t)srow * (NH * QHD) + h * QHD + NOPE;
        float x0 = base[2 * j];
        float x1 = base[2 * j + 1];
        __syncwarp();
        base[j]      = x0 * cv - x1 * sv;
        base[32 + j] = x1 * cv + x0 * sv;
    } else {
        const float* src = kpe_src + (size_t)srow * ld_src;
        float x0 = src[2 * j];
        float x1 = src[2 * j + 1];
        float* dst = kpe + (size_t)srow * ROPE_D;
        dst[j]      = x0 * cv - x1 * sv;
        dst[32 + j] = x1 * cv + x0 * sv;
    }
}

// ---------------------------------------------------------------------------
// Pack Q and K per head into hi/lo word arrays [h][s][96w]
// ---------------------------------------------------------------------------
__global__ void qk_pack_kernel(
    uint32_t* __restrict__ qh, uint32_t* __restrict__ ql,
    uint32_t* __restrict__ kh, uint32_t* __restrict__ kl,
    const float* __restrict__ q, const float* __restrict__ kv,
    const float* __restrict__ kpe)
{
    int idx = blockIdx.x * 256 + threadIdx.x;
    if (idx >= NH * S_LEN * 96) return;
    int w = idx % 96;
    int s = (idx / 96) % S_LEN;
    int h = idx / (96 * S_LEN);

    uint32_t hi, lo;
    const float* qp = q + (size_t)s * (NH * QHD) + h * QHD + 2 * w;
    split2(qp[0], qp[1], hi, lo);
    qh[idx] = hi; ql[idx] = lo;
    float a, b;
    if (w < 64) {
        const float* kp = kv + (size_t)s * (NH * 256) + h * 256 + 2 * w;
        a = kp[0]; b = kp[1];
    } else {
        const float* kp = kpe + (size_t)s * ROPE_D + 2 * (w - 64);
        a = kp[0]; b = kp[1];
    }
    split2(a, b, hi, lo);
    kh[idx] = hi; kl[idx] = lo;
}

// ---------------------------------------------------------------------------
// Pack V transposed: g_kv -> vt [h][vd][s/2 words]
// ---------------------------------------------------------------------------
__global__ void vt_pack_kernel(uint32_t* __restrict__ vth, uint32_t* __restrict__ vtl,
                               const float* __restrict__ kv)
{
    __shared__ float tile[64][33];
    const int s0 = blockIdx.x * 64, v0 = blockIdx.y * 32, h = blockIdx.z;
    const int tid = threadIdx.x;
#pragma unroll
    for (int i = 0; i < 8; i++) {
        int e = tid + i * 256;
        int s = e >> 5, vd = e & 31;
        tile[s][vd] = kv[(size_t)(s0 + s) * (NH * 256) + h * 256 + NOPE + v0 + vd];
    }
    __syncthreads();
#pragma unroll
    for (int i = 0; i < 4; i++) {
        int e = tid + i * 256;
        int vd = e >> 5, sw_ = e & 31;
        uint32_t hi, lo;
        split2(tile[2 * sw_][vd], tile[2 * sw_ + 1][vd], hi, lo);
        size_t o = (size_t)(h * VD + v0 + vd) * (S_LEN / 2) + (s0 >> 1) + sw_;
        vth[o] = hi; vtl[o] = lo;
    }
}

// ---------------------------------------------------------------------------
// Tensor-core causal flash attention (3-term bf16, fp32 softmax/acc).
// ---------------------------------------------------------------------------
#define FLASH_SMEM_BYTES (52480 * 4)

__global__ void __launch_bounds__(256, 1) flash_mma_kernel(
    uint32_t* __restrict__ Oh, uint32_t* __restrict__ Ol,
    const uint32_t* __restrict__ Qh, const uint32_t* __restrict__ Ql,
    const uint32_t* __restrict__ Kh, const uint32_t* __restrict__ Kl,
    const uint32_t* __restrict__ Vh, const uint32_t* __restrict__ Vl)
{
    extern __shared__ uint32_t sw[];
    uint32_t* sQh = sw;
    uint32_t* sQl = sw + 6400;
    uint32_t* sKh = sw + 12800;
    uint32_t* sKl = sw + 25600;
    uint32_t* sVh = sw + 38400;
    uint32_t* sVl = sw + 43008;
    uint32_t* sPh = sw + 47616;
    uint32_t* sPl = sw + 49920;
    float*    sMax = (float*)(sw + 52224);
    float*    sSum = sMax + 128;

    const int tid  = threadIdx.x;
    const int lane = tid & 31;
    const int w    = tid >> 5;
    const int wm   = w & 3;
    const int wn   = w >> 2;
    const int g    = lane >> 2;
    const int t    = lane & 3;
    const int h    = blockIdx.y;
    const int qb   = blockIdx.x;
    const int q0   = qb * 64;
    const uint32_t sb = (uint32_t)__cvta_generic_to_shared(sw);

    const uint32_t* Qhp = Qh + ((size_t)h * S_LEN + q0) * 96;
    const uint32_t* Qlp = Ql + ((size_t)h * S_LEN + q0) * 96;
    const uint32_t* Khp = Kh + (size_t)h * S_LEN * 96;
    const uint32_t* Klp = Kl + (size_t)h * S_LEN * 96;
    const uint32_t* Vhp = Vh + (size_t)h * VD * (S_LEN / 2);
    const uint32_t* Vlp = Vl + (size_t)h * VD * (S_LEN / 2);

#pragma unroll
    for (int i = 0; i < 6; i++) {
        int c = tid + i * 256;
        int r = c / 24, c4 = (c % 24) * 4;
        CP16(sb + (r * 100 + c4) * 4,           Qhp + r * 96 + c4);
        CP16(sb + (6400 + r * 100 + c4) * 4,    Qlp + r * 96 + c4);
        CP16(sb + (12800 + r * 100 + c4) * 4,   Khp + r * 96 + c4);
        CP16(sb + (25600 + r * 100 + c4) * 4,   Klp + r * 96 + c4);
    }
    CP_COMMIT();

    float oacc[8][4];
#pragma unroll
    for (int ni = 0; ni < 8; ni++)
#pragma unroll
        for (int e = 0; e < 4; e++) oacc[ni][e] = 0.f;
    float mi0 = -1e30f, mi1 = -1e30f, li0 = 0.f, li1 = 0.f;

    const int r0 = wm * 16 + g, r1 = r0 + 8;
    const int qi0 = q0 + r0, qi1 = q0 + r1;
    const float scale = rsqrtf((float)QHD);

    for (int kb = 0; kb <= qb; kb++) {
        const int k0 = kb * 64;
#pragma unroll
        for (int i = 0; i < 4; i++) {
            int c = tid + i * 256;
            int r = c >> 3, c4 = (c & 7) * 4;
            CP16(sb + (38400 + r * 36 + c4) * 4, Vhp + (size_t)r * (S_LEN/2) + (k0 >> 1) + c4);
            CP16(sb + (43008 + r * 36 + c4) * 4, Vlp + (size_t)r * (S_LEN/2) + (k0 >> 1) + c4);
        }
        CP_COMMIT();
        if (kb < qb) {
            const int kn = (kb + 1) * 64;
            const int bo = ((kb + 1) & 1) * 6400;
#pragma unroll
            for (int i = 0; i < 6; i++) {
                int c = tid + i * 256;
                int r = c / 24, c4 = (c % 24) * 4;
                CP16(sb + (12800 + bo + r * 100 + c4) * 4, Khp + (size_t)(kn + r) * 96 + c4);
                CP16(sb + (25600 + bo + r * 100 + c4) * 4, Klp + (size_t)(kn + r) * 96 + c4);
            }
            CP_COMMIT();
            asm volatile("cp.async.wait_group 2;");
        } else {
            asm volatile("cp.async.wait_group 1;");
        }
        __syncthreads();

        const uint32_t* kbh = sKh + (kb & 1) * 6400;
        const uint32_t* kbl = sKl + (kb & 1) * 6400;
        float sacc[4][4];
#pragma unroll
        for (int ni = 0; ni < 4; ni++)
#pragma unroll
            for (int e = 0; e < 4; e++) sacc[ni][e] = 0.f;

#pragma unroll
        for (int ka = 0; ka < 12; ka++) {
            uint32_t bh[4][2], bl[4][2];
#pragma unroll
            for (int ni = 0; ni < 4; ni++) {
                int ba = (wn * 32 + ni * 8 + g) * 100 + ka * 8 + t;
                bh[ni][0] = kbh[ba]; bh[ni][1] = kbh[ba + 4];
                bl[ni][0] = kbl[ba]; bl[ni][1] = kbl[ba + 4];
            }
            int aa = r0 * 100 + ka * 8 + t;
            uint32_t ah[4], al[4];
            ah[0] = sQh[aa]; ah[1] = sQh[aa + 800]; ah[2] = sQh[aa + 4]; ah[3] = sQh[aa + 804];
            al[0] = sQl[aa]; al[1] = sQl[aa + 800]; al[2] = sQl[aa + 4]; al[3] = sQl[aa + 804];
#pragma unroll
            for (int ni = 0; ni < 4; ni++) {
                mma_bf16(sacc[ni], ah, bh[ni]);
                mma_bf16(sacc[ni], al, bh[ni]);
                mma_bf16(sacc[ni], ah, bl[ni]);
            }
        }

        const bool diag = (kb == qb);
        float v0[8], v1[8];
        float rm0 = -1e30f, rm1 = -1e30f;
#pragma unroll
        for (int ni = 0; ni < 4; ni++) {
#pragma unroll
            for (int e = 0; e < 2; e++) {
                int col = k0 + wn * 32 + ni * 8 + 2 * t + e;
                float x0 = sacc[ni][e]     * scale;
                float x1 = sacc[ni][2 + e] * scale;
                if (diag && col > qi0) x0 = -1e30f;
                if (diag && col > qi1) x1 = -1e30f;
                v0[ni * 2 + e] = x0;
                v1[ni * 2 + e] = x1;
                rm0 = fmaxf(rm0, x0);
                rm1 = fmaxf(rm1, x1);
            }
        }
        rm0 = fmaxf(rm0, __shfl_xor_sync(0xffffffffu, rm0, 1));
        rm0 = fmaxf(rm0, __shfl_xor_sync(0xffffffffu, rm0, 2));
        rm1 = fmaxf(rm1, __shfl_xor_sync(0xffffffffu, rm1, 1));
        rm1 = fmaxf(rm1, __shfl_xor_sync(0xffffffffu, rm1, 2));
        if (t == 0) {
            sMax[r0 * 2 + wn] = rm0;
            sMax[r1 * 2 + wn] = rm1;
        }
        __syncthreads();
        float mn0 = fmaxf(mi0, fmaxf(sMax[r0 * 2], sMax[r0 * 2 + 1]));
        float mn1 = fmaxf(mi1, fmaxf(sMax[r1 * 2], sMax[r1 * 2 + 1]));
        float al0 = __expf(mi0 - mn0);
        float al1 = __expf(mi1 - mn1);
        float ls0 = 0.f, ls1 = 0.f;
#pragma unroll
        for (int i = 0; i < 8; i++) {
            v0[i] = __expf(v0[i] - mn0); ls0 += v0[i];
            v1[i] = __expf(v1[i] - mn1); ls1 += v1[i];
        }
#pragma unroll
        for (int ni = 0; ni < 4; ni++) {
            uint32_t hi, lo;
            split2(v0[ni * 2], v0[ni * 2 + 1], hi, lo);
            sPh[r0 * 36 + wn * 16 + ni * 4 + t] = hi;
            sPl[r0 * 36 + wn * 16 + ni * 4 + t] = lo;
            split2(v1[ni * 2], v1[ni * 2 + 1], hi, lo);
            sPh[r1 * 36 + wn * 16 + ni * 4 + t] = hi;
            sPl[r1 * 36 + wn * 16 + ni * 4 + t] = lo;
        }
        ls0 += __shfl_xor_sync(0xffffffffu, ls0, 1);
        ls0 += __shfl_xor_sync(0xffffffffu, ls0, 2);
        ls1 += __shfl_xor_sync(0xffffffffu, ls1, 1);
        ls1 += __shfl_xor_sync(0xffffffffu, ls1, 2);
        if (t == 0) {
            sSum[r0 * 2 + wn] = ls0;
            sSum[r1 * 2 + wn] = ls1;
        }
        __syncthreads();
        li0 = li0 * al0 + sSum[r0 * 2] + sSum[r0 * 2 + 1];
        li1 = li1 * al1 + sSum[r1 * 2] + sSum[r1 * 2 + 1];
        mi0 = mn0; mi1 = mn1;
#pragma unroll
        for (int ni = 0; ni < 8; ni++) {
            oacc[ni][0] *= al0; oacc[ni][1] *= al0;
            oacc[ni][2] *= al1; oacc[ni][3] *= al1;
        }
        if (kb < qb) asm volatile("cp.async.wait_group 1;");
        else         asm volatile("cp.async.wait_group 0;");
        __syncthreads();

#pragma unroll
        for (int ka = 0; ka < 4; ka++) {
            int aa = r0 * 36 + ka * 8 + t;
            uint32_t ah[4], al[4];
            ah[0] = sPh[aa]; ah[1] = sPh[aa + 288]; ah[2] = sPh[aa + 4]; ah[3] = sPh[aa + 292];
            al[0] = sPl[aa]; al[1] = sPl[aa + 288]; al[2] = sPl[aa + 4]; al[3] = sPl[aa + 292];
#pragma unroll
            for (int ni = 0; ni < 8; ni++) {
                int ba = (wn * 64 + ni * 8 + g) * 36 + ka * 8 + t;
                uint32_t bh[2], bl[2];
                bh[0] = sVh[ba]; bh[1] = sVh[ba + 4];
                bl[0] = sVl[ba]; bl[1] = sVl[ba + 4];
                mma_bf16(oacc[ni], ah, bh);
                mma_bf16(oacc[ni], al, bh);
                mma_bf16(oacc[ni], ah, bl);
            }
        }
        __syncthreads();
    }

    float inv0 = 1.f / li0, inv1 = 1.f / li1;
#pragma unroll
    for (int ni = 0; ni < 8; ni++) {
        int col  = h * VD + wn * 64 + ni * 8 + 2 * t;
        int word = col >> 1;
        uint32_t hi, lo;
        split2(oacc[ni][0] * inv0, oacc[ni][1] * inv0, hi, lo);
        Oh[(size_t)(q0 + r0) * (NH * VD / 2) + word] = hi;
        Ol[(size_t)(q0 + r0) * (NH * VD / 2) + word] = lo;
        split2(oacc[ni][2] * inv1, oacc[ni][3] * inv1, hi, lo);
        Oh[(size_t)(q0 + r1) * (NH * VD / 2) + word] = hi;
        Ol[(size_t)(q0 + r1) * (NH * VD / 2) + word] = lo;
    }
}

// ---------------------------------------------------------------------------
// Launch
// ---------------------------------------------------------------------------
extern "C" void kernel_launch(void* const* d_in, const int* in_sizes, int n_in,
                              void* d_out, int out_size)
{
    const float* hidden = (const float*)d_in[0];
    const int*   pos    = (const int*)d_in[1];
    const float* Wqa    = (const float*)d_in[2];
    const float* qa_ln  = (const float*)d_in[3];
    const float* Wqb    = (const float*)d_in[4];
    const float* Wkva   = (const float*)d_in[5];
    const float* kv_ln  = (const float*)d_in[6];
    const float* Wkvb   = (const float*)d_in[7];
    const float* Wo     = (const float*)d_in[8];
    float* out = (float*)d_out;

    float *qackv, *q, *kpe, *kv;
    cudaGetSymbolAddress((void**)&qackv, g_qackv);
    cudaGetSymbolAddress((void**)&q,     g_q);
    cudaGetSymbolAddress((void**)&kpe,   g_kpe);
    cudaGetSymbolAddress((void**)&kv,    g_kv);

    uint32_t *hidh, *hidl, *qanh, *qanl, *ckvnh, *ckvnl, *attnh, *attnl;
    uint32_t *W12th, *W12tl, *Wqbth, *Wqbtl, *Wkvbth, *Wkvbtl, *Woth, *Wotl;
    uint32_t *qph, *qpl, *kph, *kpl, *vth, *vtl;
    cudaGetSymbolAddress((void**)&hidh,  g_hidh);
    cudaGetSymbolAddress((void**)&hidl,  g_hidl);
    cudaGetSymbolAddress((void**)&qanh,  g_qanh);
    cudaGetSymbolAddress((void**)&qanl,  g_qanl);
    cudaGetSymbolAddress((void**)&ckvnh, g_ckvnh);
    cudaGetSymbolAddress((void**)&ckvnl, g_ckvnl);
    cudaGetSymbolAddress((void**)&attnh, g_attnh);
    cudaGetSymbolAddress((void**)&attnl, g_attnl);
    cudaGetSymbolAddress((void**)&W12th,  g_W12th);
    cudaGetSymbolAddress((void**)&W12tl,  g_W12tl);
    cudaGetSymbolAddress((void**)&Wqbth,  g_Wqbth);
    cudaGetSymbolAddress((void**)&Wqbtl,  g_Wqbtl);
    cudaGetSymbolAddress((void**)&Wkvbth, g_Wkvbth);
    cudaGetSymbolAddress((void**)&Wkvbtl, g_Wkvbtl);
    cudaGetSymbolAddress((void**)&Woth,   g_Woth);
    cudaGetSymbolAddress((void**)&Wotl,   g_Wotl);
    cudaGetSymbolAddress((void**)&qph, g_qph);
    cudaGetSymbolAddress((void**)&qpl, g_qpl);
    cudaGetSymbolAddress((void**)&kph, g_kph);
    cudaGetSymbolAddress((void**)&kpl, g_kpl);
    cudaGetSymbolAddress((void**)&vth, g_vth);
    cudaGetSymbolAddress((void**)&vtl, g_vtl);

    cudaFuncSetAttribute(gemm_bf16x3_ldsm_kernel,
                         cudaFuncAttributeMaxDynamicSharedMemorySize, GEMM_SMEM_BYTES);
    cudaFuncSetAttribute(flash_mma_kernel,
                         cudaFuncAttributeMaxDynamicSharedMemorySize, FLASH_SMEM_BYTES);

    // ---- batched weight transpose+split (1 launch, 5 jobs) ----
    WtJobs jobs;
    // Wqa: rows 0..1535 of combined
    jobs.j[0] = { Wqa,  W12th,               W12tl,               HID,  QLR,          48,  0 };
    // Wkva: rows 1536..2175 of combined
    jobs.j[1] = { Wkva, W12th + 1536*(HID/2), W12tl + 1536*(HID/2), HID, CKVD,        20,  3072 };
    jobs.j[2] = { Wqb,  Wqbth,               Wqbtl,               QLR,  NH * QHD,     96,  4352 };
    jobs.j[3] = { Wkvb, Wkvbth,              Wkvbtl,              KVLR, NH*(NOPE+VD), 128, 8960 };
    jobs.j[4] = { Wo,   Woth,                Wotl,                NH*VD, HID,         64,  11008 };
    jobs.total = 15104;
    wt_split_all_kernel<<<jobs.total, dim3(32, 8)>>>(jobs);

    split_pack_kernel<<<(S_LEN * (HID/2) + 255) / 256, 256>>>(hidh, hidl, hidden, S_LEN * (HID/2));

    // 1+2) [qa | ckv] = hidden @ [Wqa | Wkva]   (grid 17x16 = 272 CTAs)
    gemm_bf16x3_ldsm_kernel<<<dim3(NC12 / 128, S_LEN / 128), 256, GEMM_SMEM_BYTES>>>(
        qackv, hidh, hidl, W12th, W12tl, S_LEN, NC12V, HID, NC12);
    // 3-4) rmsnorms -> packed (from combined buffer)
    rmsnorm_pack_kernel<<<S_LEN, 256>>>(qanh, qanl, qackv, qa_ln, QLR, NC12);
    rmsnorm_pack_kernel<<<S_LEN, 256>>>(ckvnh, ckvnl, qackv + QLR, kv_ln, KVLR, NC12);
    // 5) q = q_a_n @ Wqb
    gemm_bf16x3_ldsm_kernel<<<dim3(3072 / 128, S_LEN / 128), 256, GEMM_SMEM_BYTES>>>(
        q, qanh, qanl, Wqbth, Wqbtl, S_LEN, NH * QHD, QLR, NH * QHD);
    // 6) kv = ckv_n @ Wkvb
    gemm_bf16x3_ldsm_kernel<<<dim3(4096 / 128, S_LEN / 128), 256, GEMM_SMEM_BYTES>>>(
        kv, ckvnh, ckvnl, Wkvbth, Wkvbtl, S_LEN, NH * 256, KVLR, NH * 256);
    // 7) RoPE (k_pe from combined buffer cols [2048, 2112))
    rope_kernel<<<S_LEN, (NH + 1) * 32>>>(q, kpe, qackv + QLR + KVLR, NC12, pos);
    // 8) pack flash inputs
    qk_pack_kernel<<<(NH * S_LEN * 96 + 255) / 256, 256>>>(qph, qpl, kph, kpl, q, kv, kpe);
    vt_pack_kernel<<<dim3(S_LEN / 64, VD / 32, NH), 256>>>(vth, vtl, kv);
    // 9) tensor-core flash attention
    flash_mma_kernel<<<dim3(S_LEN / 64, NH), 256, FLASH_SMEM_BYTES>>>(
        attnh, attnl, qph, qpl, kph, kpl, vth, vtl);
    // 10) out = attn @ Wo
    gemm_bf16x3_ldsm_kernel<<<dim3(HID / 128, S_LEN / 128), 256, GEMM_SMEM_BYTES>>>(
        out, attnh, attnl, Woth, Wotl, S_LEN, HID, NH * VD, HID);
}